// round 5
// baseline (speedup 1.0000x reference)
#include <cuda_runtime.h>
#include <cuda_bf16.h>
#include <math.h>
#include <stdint.h>

#define NV   50257
#define NPAD 50304          // 393 * 128
#define DD   128
#define BB_  2048
#define CC   10

// Does THIS compilation pass support tcgen05? (sm_103a / sm_100a arch-specific,
// or family-specific). Plain sm_103 pass compiles the mma.sync fallback.
#if defined(__CUDA_ARCH__) && (defined(__CUDA_ARCH_FEAT_SM103_ALL) || \
    defined(__CUDA_ARCH_FEAT_SM100_ALL) || defined(__CUDA_ARCH_FAMILY_SPECIFIC__))
#define HAS_TCGEN05 1
#else
#define HAS_TCGEN05 0
#endif

// ---------------- scratch (static __device__ — allocation-free) ----------------
__device__ __align__(16) __nv_bfloat16 g_zb[BB_ * DD];    // z in bf16
__device__ float g_S[BB_];                                // sum exp(logits) per row
__device__ float g_R[BB_];                                // sum of picked logits per row
__device__ float g_kl[BB_];

// ---------------- common helpers ----------------
__device__ __forceinline__ uint32_t smem_to_u32(const void* p) {
    uint32_t a;
    asm("{ .reg .u64 t; cvta.to.shared.u64 t, %1; cvt.u32.u64 %0, t; }"
        : "=r"(a) : "l"(p));
    return a;
}
__device__ __forceinline__ float softplusf(float x) {
    return fmaxf(x, 0.f) + log1pf(expf(-fabsf(x)));
}

// ---------------- kernel 1: inference network + KL + z + ctx-logits ----------------
#define WT_LD 136
__global__ void __launch_bounds__(128) k_infnet(
    const int* __restrict__ x_batch, const int* __restrict__ ctx,
    const float* __restrict__ eps, const float* __restrict__ inf_emb,
    const float* __restrict__ W_aff, const float* __restrict__ b_aff,
    const float* __restrict__ W_mu,  const float* __restrict__ b_mu,
    const float* __restrict__ W_sig, const float* __restrict__ b_sig,
    const float* __restrict__ gen_sigma_emb,
    const float* __restrict__ W_gen, const float* __restrict__ b_gen)
{
    extern __shared__ float sm[];
    float* Wt   = sm;                       // 256*136 floats
    float* embs = sm + 256 * WT_LD;         // 176*128 floats

    const int tid  = threadIdx.x;
    const int w    = tid >> 5;
    const int lane = tid & 31;
    const int b0   = blockIdx.x * 16;

    if (tid < 16) { g_S[b0 + tid] = 0.f; g_R[b0 + tid] = 0.f; }

    for (int idx = tid; idx < 128 * 256; idx += 128) {
        int d = idx >> 8, e = idx & 255;
        Wt[e * WT_LD + d] = W_aff[idx];
    }
    for (int r = w; r < 176; r += 4) {
        int b = r / 11, j = r - b * 11;
        int bg = b0 + b;
        int word = (j == 0) ? x_batch[bg] : ctx[bg * CC + (j - 1)];
        const float4* src = (const float4*)(inf_emb + (size_t)word * DD);
        ((float4*)(embs + r * 128))[lane] = src[lane];
    }
    __syncthreads();

    const int d0 = lane * 4;
    float4 ba = *(const float4*)(b_aff + d0);

    int bl[4];
    const float* cbase[4];
#pragma unroll
    for (int bb = 0; bb < 4; bb++) {
        bl[bb] = w + bb * 4;
        cbase[bb] = embs + (bl[bb] * 11) * 128;
    }

    float s0[4][4];
#pragma unroll
    for (int bb = 0; bb < 4; bb++) {
        s0[bb][0] = ba.x; s0[bb][1] = ba.y; s0[bb][2] = ba.z; s0[bb][3] = ba.w;
    }
#pragma unroll 4
    for (int e = 0; e < 128; e++) {
        float4 wv = *(const float4*)(Wt + e * WT_LD + d0);
#pragma unroll
        for (int bb = 0; bb < 4; bb++) {
            float cv = cbase[bb][e];
            s0[bb][0] += cv * wv.x; s0[bb][1] += cv * wv.y;
            s0[bb][2] += cv * wv.z; s0[bb][3] += cv * wv.w;
        }
    }

    float hsum[4][4];
#pragma unroll
    for (int bb = 0; bb < 4; bb++)
#pragma unroll
        for (int q = 0; q < 4; q++) hsum[bb][q] = 0.f;

    for (int c = 0; c < CC; c++) {
        float ha[4][4];
#pragma unroll
        for (int bb = 0; bb < 4; bb++)
#pragma unroll
            for (int q = 0; q < 4; q++) ha[bb][q] = s0[bb][q];
#pragma unroll 4
        for (int e = 0; e < 128; e++) {
            float4 wv = *(const float4*)(Wt + (128 + e) * WT_LD + d0);
#pragma unroll
            for (int bb = 0; bb < 4; bb++) {
                float cv = cbase[bb][(1 + c) * 128 + e];
                ha[bb][0] += cv * wv.x; ha[bb][1] += cv * wv.y;
                ha[bb][2] += cv * wv.z; ha[bb][3] += cv * wv.w;
            }
        }
#pragma unroll
        for (int bb = 0; bb < 4; bb++)
#pragma unroll
            for (int q = 0; q < 4; q++) hsum[bb][q] += fmaxf(ha[bb][q], 0.f);
    }

    __syncthreads();
    for (int idx = tid; idx < 128 * 128; idx += 128) {
        int d = idx >> 7, k = idx & 127;
        Wt[k * WT_LD + d]         = W_mu[idx];
        Wt[(128 + k) * WT_LD + d] = W_sig[idx];
    }
    __syncthreads();

    float4 bm = *(const float4*)(b_mu + d0);
    float4 bs = *(const float4*)(b_sig + d0);
    float mu[4][4], sg[4][4];
#pragma unroll
    for (int bb = 0; bb < 4; bb++) {
        mu[bb][0] = bm.x; mu[bb][1] = bm.y; mu[bb][2] = bm.z; mu[bb][3] = bm.w;
        sg[bb][0] = bs.x; sg[bb][1] = bs.y; sg[bb][2] = bs.z; sg[bb][3] = bs.w;
    }

    for (int ll = 0; ll < 32; ll++) {
#pragma unroll
        for (int q = 0; q < 4; q++) {
            int k = ll * 4 + q;
            float4 wm4 = *(const float4*)(Wt + k * WT_LD + d0);
            float4 ws4 = *(const float4*)(Wt + (128 + k) * WT_LD + d0);
#pragma unroll
            for (int bb = 0; bb < 4; bb++) {
                float hv = __shfl_sync(0xffffffffu, hsum[bb][q], ll);
                mu[bb][0] += hv * wm4.x; mu[bb][1] += hv * wm4.y;
                mu[bb][2] += hv * wm4.z; mu[bb][3] += hv * wm4.w;
                sg[bb][0] += hv * ws4.x; sg[bb][1] += hv * ws4.y;
                sg[bb][2] += hv * ws4.z; sg[bb][3] += hv * ws4.w;
            }
        }
    }
    __syncthreads();            // everyone done reading Wt; it becomes z scratch

    float* zsm = Wt;            // zsm[b][128], b = 0..15

#pragma unroll
    for (int bb = 0; bb < 4; bb++) {
        int bg = b0 + bl[bb];
        int xb = x_batch[bg];
        float4 ep4 = *(const float4*)(eps + (size_t)bg * DD + d0);
        float4 gs4 = *(const float4*)(gen_sigma_emb + (size_t)xb * DD + d0);
        float epv[4] = {ep4.x, ep4.y, ep4.z, ep4.w};
        float gsv[4] = {gs4.x, gs4.y, gs4.z, gs4.w};
        float zq[4];
        float klacc = 0.f;
#pragma unroll
        for (int q = 0; q < 4; q++) {
            float m   = mu[bb][q];
            float isg = softplusf(sg[bb][q]);
            float zv  = m + epv[q] * isg;
            zq[q] = zv;
            float sgm = softplusf(gsv[q]);
            float dm  = m - sgm;
            klacc += logf(sgm / isg)
                   + (isg * isg + dm * dm) / (2.f * sgm * sgm) - 0.5f;
        }
        *(float4*)(zsm + bl[bb] * 128 + d0) = make_float4(zq[0], zq[1], zq[2], zq[3]);
        __nv_bfloat162 p0 = __floats2bfloat162_rn(zq[0], zq[1]);
        __nv_bfloat162 p1 = __floats2bfloat162_rn(zq[2], zq[3]);
        ((__nv_bfloat162*)(g_zb + (size_t)bg * DD + d0))[0] = p0;
        ((__nv_bfloat162*)(g_zb + (size_t)bg * DD + d0))[1] = p1;
#pragma unroll
        for (int o = 16; o; o >>= 1) klacc += __shfl_xor_sync(0xffffffffu, klacc, o);
        if (lane == 0) g_kl[bg] = klacc;
    }
    __syncthreads();

    // ---- picked context logits (fp32): 160 (b,c) pairs over 4 warps ----
    for (int pp = w; pp < 16 * CC; pp += 4) {
        int b = pp / CC, c = pp - b * CC;
        int bg = b0 + b;
        int n  = ctx[bg * CC + c];
        float4 w4 = ((const float4*)(W_gen + (size_t)n * DD))[lane];
        float4 z4 = *(const float4*)(zsm + b * 128 + d0);
        float d = z4.x * w4.x + z4.y * w4.y + z4.z * w4.z + z4.w * w4.w;
#pragma unroll
        for (int o = 16; o; o >>= 1) d += __shfl_xor_sync(0xffffffffu, d, o);
        if (lane == 0) atomicAdd(&g_R[bg], d + b_gen[n]);
    }
}

// ======================== k_logits: two arch paths ========================
// grid = (393, 2): blockIdx.x = vocab tile (N=128), blockIdx.y picks 8 of the
// 16 batch tiles -> 786 uniform CTAs = balanced 3 rounds at 2 CTA/SM.
#define MT_PER_CTA 8

#if HAS_TCGEN05
__device__ __forceinline__ uint32_t elect_one_pred() {
    uint32_t pred;
    asm volatile(
        "{\n\t.reg .pred p;\n\t"
        "elect.sync _|p, 0xFFFFFFFF;\n\t"
        "selp.b32 %0, 1, 0, p;\n\t}"
        : "=r"(pred));
    return pred;
}
#define MBARRIER_INIT(mbar, cnt) \
    asm volatile("mbarrier.init.shared.b64 [%0], %1;" :: "r"((uint32_t)(mbar)), "r"((uint32_t)(cnt)) : "memory")
#define MBARRIER_WAIT_PARITY(mbar, par) do { \
    uint32_t _m = (uint32_t)(mbar); uint32_t _p = (uint32_t)(par); uint32_t _d; \
    asm volatile("{\n\t.reg .pred p;\n\t" \
        "mbarrier.try_wait.parity.acquire.cta.shared::cta.b64 p, [%1], %2;\n\t" \
        "selp.b32 %0, 1, 0, p;\n\t}" : "=r"(_d) : "r"(_m), "r"(_p) : "memory"); \
    if (!_d) { \
        asm volatile("{\n\t.reg .pred P1;\n\t" \
            "WL_%=:\n\t" \
            "mbarrier.try_wait.parity.acquire.cta.shared::cta.b64 P1, [%0], %1, 0x989680;\n\t" \
            "@P1 bra.uni WD_%=;\n\t" \
            "bra.uni WL_%=;\n\t" \
            "WD_%=:\n\t}" :: "r"(_m), "r"(_p) : "memory"); \
    } } while (0)
#define TCGEN05_ALLOC(smem_addr, nCols) \
    asm volatile("tcgen05.alloc.cta_group::1.sync.aligned.shared::cta.b32 [%0], %1;" \
        :: "r"((uint32_t)(smem_addr)), "r"((uint32_t)(nCols)) : "memory")
#define TCGEN05_DEALLOC(tmem, nCols) \
    asm volatile("tcgen05.dealloc.cta_group::1.sync.aligned.b32 %0, %1;" :: "r"(tmem), "r"((uint32_t)(nCols)))
#define TCGEN05_RELINQUISH() \
    asm volatile("tcgen05.relinquish_alloc_permit.cta_group::1.sync.aligned;")
#define TCGEN05_COMMIT(mbar) \
    asm volatile("tcgen05.commit.cta_group::1.mbarrier::arrive::one.shared::cluster.b64 [%0];" \
        :: "r"((uint32_t)(mbar)) : "memory")
#define TCGEN05_FENCE_BEFORE() asm volatile("tcgen05.fence::before_thread_sync;" ::: "memory")
#define TCGEN05_FENCE_AFTER()  asm volatile("tcgen05.fence::after_thread_sync;" ::: "memory")
#define TCGEN05_WAIT_LD()      asm volatile("tcgen05.wait::ld.sync.aligned;" ::: "memory")
#define FENCE_PROXY_ASYNC()    asm volatile("fence.proxy.async.shared::cta;" ::: "memory")
#define TCGEN05_LD_32X32B_X32(r, tmem_addr) \
    asm volatile( \
        "tcgen05.ld.sync.aligned.32x32b.x32.b32 " \
        "{%0, %1, %2, %3, %4, %5, %6, %7, " \
        " %8, %9, %10, %11, %12, %13, %14, %15, " \
        " %16, %17, %18, %19, %20, %21, %22, %23, " \
        " %24, %25, %26, %27, %28, %29, %30, %31}, [%32];" \
        : "=r"((r)[0]),  "=r"((r)[1]),  "=r"((r)[2]),  "=r"((r)[3]), \
          "=r"((r)[4]),  "=r"((r)[5]),  "=r"((r)[6]),  "=r"((r)[7]), \
          "=r"((r)[8]),  "=r"((r)[9]),  "=r"((r)[10]), "=r"((r)[11]), \
          "=r"((r)[12]), "=r"((r)[13]), "=r"((r)[14]), "=r"((r)[15]), \
          "=r"((r)[16]), "=r"((r)[17]), "=r"((r)[18]), "=r"((r)[19]), \
          "=r"((r)[20]), "=r"((r)[21]), "=r"((r)[22]), "=r"((r)[23]), \
          "=r"((r)[24]), "=r"((r)[25]), "=r"((r)[26]), "=r"((r)[27]), \
          "=r"((r)[28]), "=r"((r)[29]), "=r"((r)[30]), "=r"((r)[31]) \
        : "r"(tmem_addr))
static constexpr uint64_t SMEM_DESC_BASE_SW128 =
    (uint64_t(2) << 61) | (uint64_t(1) << 46) | (uint64_t(64) << 32) | (uint64_t(1) << 16);
#define MAKE_SMEM_DESC(addr) (SMEM_DESC_BASE_SW128 | ((uint64_t)((addr) >> 4) & 0x3FFF))
#define IDESC_LOG 0x08200490u   // f32 accum, bf16 x bf16, M=128, N=128

__device__ __forceinline__ void mma_f16_ss(uint32_t d_tmem, uint64_t a_desc,
                                           uint64_t b_desc, uint32_t idesc, bool accum) {
    uint32_t en = accum ? 1u : 0u;
    asm volatile(
        "{\n\t.reg .pred p;\n\t"
        "setp.ne.u32 p, %4, 0;\n\t"
        "tcgen05.mma.cta_group::1.kind::f16 [%0], %1, %2, %3, {%5,%5,%5,%5}, p;\n\t}"
        :: "r"(d_tmem), "l"(a_desc), "l"(b_desc), "r"(idesc), "r"(en), "r"(0u)
        : "memory");
}

#define SM_TPTR  0
#define SM_MBAR0 8
#define SM_MBAR1 16
#define SM_BG    32
#define SM_W     1024
#define SM_Z0    (1024 + 32768)
#define SM_Z1    (1024 + 65536)

__device__ __forceinline__ void logits_epilogue(int lt, int mt, uint32_t sb, uint32_t tmem,
                                                const float* bg_s, int w, int lane) {
    const int q = lt & 1;
    MBARRIER_WAIT_PARITY(sb + (q ? SM_MBAR1 : SM_MBAR0), (lt >> 1) & 1);
    TCGEN05_FENCE_AFTER();
    const uint32_t woff = ((uint32_t)(w & 3)) << 21;
    const int cb = (w < 4) ? 0 : 64;
    const uint32_t dt = tmem + (uint32_t)(q * 128 + cb) + woff;
    uint32_t r0[32], r1[32];
    TCGEN05_LD_32X32B_X32(r0, dt);
    TCGEN05_LD_32X32B_X32(r1, dt + 32);
    TCGEN05_WAIT_LD();
    TCGEN05_FENCE_BEFORE();
    float acc = 0.f;
#pragma unroll
    for (int c = 0; c < 32; c++) acc += __expf(__uint_as_float(r0[c]) + bg_s[cb + c]);
#pragma unroll
    for (int c = 0; c < 32; c++) acc += __expf(__uint_as_float(r1[c]) + bg_s[cb + 32 + c]);
    atomicAdd(&g_S[mt * 128 + (w & 3) * 32 + lane], acc);
}
#endif  // HAS_TCGEN05

// ---- fallback helpers (baseline sm_103: mma.sync + ldmatrix + cp.async) ----
__device__ __forceinline__ void mma16816(float c[4], const uint32_t a[4],
                                         uint32_t b0, uint32_t b1) {
    asm volatile(
        "mma.sync.aligned.m16n8k16.row.col.f32.bf16.bf16.f32 "
        "{%0,%1,%2,%3},{%4,%5,%6,%7},{%8,%9},{%0,%1,%2,%3};\n"
        : "+f"(c[0]), "+f"(c[1]), "+f"(c[2]), "+f"(c[3])
        : "r"(a[0]), "r"(a[1]), "r"(a[2]), "r"(a[3]), "r"(b0), "r"(b1));
}
__device__ __forceinline__ void ldmatrix_x4(uint32_t r[4], uint32_t addr) {
    asm volatile("ldmatrix.sync.aligned.m8n8.x4.shared.b16 {%0,%1,%2,%3}, [%4];"
        : "=r"(r[0]), "=r"(r[1]), "=r"(r[2]), "=r"(r[3]) : "r"(addr));
}
#define CP_ASYNC16(dst, src) \
    asm volatile("cp.async.cg.shared.global [%0], [%1], 16;" :: "r"(dst), "l"(src))
#define CP_COMMIT()  asm volatile("cp.async.commit_group;" ::: "memory")
#define CP_WAIT(n)   asm volatile("cp.async.wait_group %0;" :: "n"(n) : "memory")

#define TLD    136
#define FB_WS  69632
#define FB_BG  104448
#define SMEM_LOG 104960   // covers both paths (tcgen05 path needs 99328)

__device__ __forceinline__ void fb_prefetch(uint32_t sb, int mt, int p, int tid) {
#pragma unroll
    for (int idx = tid; idx < 2048; idx += 256) {
        int r = idx >> 4, c = idx & 15;
        uint32_t dst = sb + (uint32_t)(p * 34816 + (r * TLD + c * 8) * 2);
        const void* src = (const void*)(g_zb + (size_t)(mt * 128 + r) * DD + c * 8);
        CP_ASYNC16(dst, src);
    }
    CP_COMMIT();
}

__global__ void __launch_bounds__(256, 2) k_logits(const float* __restrict__ W_gen,
                                                   const float* __restrict__ b_gen) {
#if HAS_TCGEN05
    // ---------------- tcgen05 path ----------------
    extern __shared__ __align__(16) char smem[];
    const uint32_t sb = smem_to_u32(smem);
    const int tid  = threadIdx.x;
    const int w    = tid >> 5;
    const int lane = tid & 31;
    const int n0   = blockIdx.x * 128;
    const int mt0  = blockIdx.y * MT_PER_CTA;

    if (w == 0) { TCGEN05_ALLOC(sb + SM_TPTR, 256); TCGEN05_RELINQUISH(); }
    if (tid == 0) { MBARRIER_INIT(sb + SM_MBAR0, 1); MBARRIER_INIT(sb + SM_MBAR1, 1); }

    for (int gidx = tid; gidx < 2048; gidx += 256) {
        int r  = gidx >> 4;
        int g8 = gidx & 15;
        int n  = n0 + r;
        uint4 outv = make_uint4(0u, 0u, 0u, 0u);
        if (n < NV) {
            const float4* src = (const float4*)(W_gen + (size_t)n * DD + g8 * 8);
            float4 f0 = src[0], f1 = src[1];
            __nv_bfloat162 h0 = __floats2bfloat162_rn(f0.x, f0.y);
            __nv_bfloat162 h1 = __floats2bfloat162_rn(f0.z, f0.w);
            __nv_bfloat162 h2 = __floats2bfloat162_rn(f1.x, f1.y);
            __nv_bfloat162 h3 = __floats2bfloat162_rn(f1.z, f1.w);
            outv.x = *(uint32_t*)&h0; outv.y = *(uint32_t*)&h1;
            outv.z = *(uint32_t*)&h2; outv.w = *(uint32_t*)&h3;
        }
        int half = g8 >> 3;
        uint32_t boff = (uint32_t)(r * 128 + (g8 & 7) * 16);
        uint32_t sw = boff ^ ((boff >> 3) & 0x70);
        *(uint4*)(smem + SM_W + half * 16384 + sw) = outv;
    }
    if (tid < 128) {
        int n = n0 + tid;
        ((float*)(smem + SM_BG))[tid] = (n < NV) ? b_gen[n] : -88.0f;
    }
    FENCE_PROXY_ASYNC();
    __syncthreads();

    uint32_t tmem;
    asm volatile("ld.shared.b32 %0, [%1];" : "=r"(tmem) : "r"(sb + SM_TPTR));
    const float* bg_s = (const float*)(smem + SM_BG);

    const uint64_t bd0 = MAKE_SMEM_DESC(sb + SM_W);
    const uint64_t bd1 = MAKE_SMEM_DESC(sb + SM_W + 16384);

    for (int lt = 0; lt < MT_PER_CTA; lt++) {
        const int mt = mt0 + lt;
        const int p = lt & 1, k = lt >> 1;
        const uint32_t zoff = p ? SM_Z1 : SM_Z0;
        if (lt >= 2) MBARRIER_WAIT_PARITY(sb + (p ? SM_MBAR1 : SM_MBAR0), (k - 1) & 1);
        for (int gidx = tid; gidx < 2048; gidx += 256) {
            int r = gidx >> 4, g8 = gidx & 15;
            uint4 val = *(const uint4*)(g_zb + ((size_t)(mt * 128 + r)) * DD + g8 * 8);
            int half = g8 >> 3;
            uint32_t boff = (uint32_t)(r * 128 + (g8 & 7) * 16);
            uint32_t sw = boff ^ ((boff >> 3) & 0x70);
            *(uint4*)(smem + zoff + half * 16384 + sw) = val;
        }
        FENCE_PROXY_ASYNC();
        __syncthreads();
        if (w == 0) {
            TCGEN05_FENCE_AFTER();
            if (elect_one_pred()) {
                const uint64_t ad0 = MAKE_SMEM_DESC(sb + zoff);
                const uint64_t ad1 = MAKE_SMEM_DESC(sb + zoff + 16384);
                const uint32_t dt = tmem + (uint32_t)(p * 128);
#pragma unroll
                for (int s = 0; s < 8; s++) {
                    uint64_t ad = ((s >> 2) ? ad1 : ad0) + (uint64_t)((s & 3) * 2);
                    uint64_t bd = ((s >> 2) ? bd1 : bd0) + (uint64_t)((s & 3) * 2);
                    mma_f16_ss(dt, ad, bd, IDESC_LOG, s > 0);
                }
                TCGEN05_COMMIT(sb + (p ? SM_MBAR1 : SM_MBAR0));
            }
        }
        if (lt >= 1) logits_epilogue(lt - 1, mt - 1, sb, tmem, bg_s, w, lane);
    }
    logits_epilogue(MT_PER_CTA - 1, mt0 + MT_PER_CTA - 1, sb, tmem, bg_s, w, lane);
    __syncthreads();
    if (w == 0) TCGEN05_DEALLOC(tmem, 256);
#else
    // ---------------- fallback: mma.sync + ldmatrix + cp.async double buffer ----
    extern __shared__ __align__(16) char smem[];
    const uint32_t sb = smem_to_u32(smem);
    __nv_bfloat16* Ws = (__nv_bfloat16*)(smem + FB_WS);
    float* bg_s = (float*)(smem + FB_BG);

    const int tid = threadIdx.x;
    const int n0  = blockIdx.x * 128;
    const int mt0 = blockIdx.y * MT_PER_CTA;

    for (int gidx = tid; gidx < 2048; gidx += 256) {
        int r = gidx >> 4, c = gidx & 15;
        int n = n0 + r;
        uint4 outv = make_uint4(0u, 0u, 0u, 0u);
        if (n < NV) {
            const float4* src = (const float4*)(W_gen + (size_t)n * DD + c * 8);
            float4 f0 = src[0], f1 = src[1];
            __nv_bfloat162 h0 = __floats2bfloat162_rn(f0.x, f0.y);
            __nv_bfloat162 h1 = __floats2bfloat162_rn(f0.z, f0.w);
            __nv_bfloat162 h2 = __floats2bfloat162_rn(f1.x, f1.y);
            __nv_bfloat162 h3 = __floats2bfloat162_rn(f1.z, f1.w);
            outv.x = *(uint32_t*)&h0; outv.y = *(uint32_t*)&h1;
            outv.z = *(uint32_t*)&h2; outv.w = *(uint32_t*)&h3;
        }
        *(uint4*)(Ws + r * TLD + c * 8) = outv;
    }
    if (tid < 128) {
        int n = n0 + tid;
        bg_s[tid] = (n < NV) ? b_gen[n] : -88.0f;
    }

    const int w    = tid >> 5;
    const int lane = tid & 31;
    const int g    = lane >> 2;
    const int t    = lane & 3;
    const int wm   = w & 3;
    const int wn   = w >> 2;

    // ldmatrix lane address components (byte offsets; bf16 = 2B)
    // A tiles: rows m0 + (lane&15), col half (lane&16)>>1 elems -> *2 bytes
    const uint32_t aLane = (uint32_t)(((wm * 32 + (lane & 15)) * TLD + ((lane & 16) >> 1)) * 2);
    // B tiles (per j-pair jp): rows wn*64 + jp*16 + ((lane&16)>>1) + (lane&7), col (lane&8)
    uint32_t bAddr[4];
#pragma unroll
    for (int jp = 0; jp < 4; jp++)
        bAddr[jp] = sb + FB_WS +
            (uint32_t)(((wn * 64 + jp * 16 + ((lane & 16) >> 1) + (lane & 7)) * TLD + (lane & 8)) * 2);

    fb_prefetch(sb, mt0, 0, tid);

    for (int lt = 0; lt < MT_PER_CTA; lt++) {
        const int p = lt & 1;
        if (lt + 1 < MT_PER_CTA) { fb_prefetch(sb, mt0 + lt + 1, p ^ 1, tid); CP_WAIT(1); }
        else                     { CP_WAIT(0); }
        __syncthreads();
        const uint32_t aBase0 = sb + (uint32_t)(p * 34816) + aLane;
        const uint32_t aBase1 = aBase0 + (uint32_t)(16 * TLD * 2);

        float acc[2][8][4];
#pragma unroll
        for (int i = 0; i < 2; i++)
#pragma unroll
            for (int j = 0; j < 8; j++)
#pragma unroll
                for (int q = 0; q < 4; q++) acc[i][j][q] = 0.f;

#pragma unroll
        for (int kk = 0; kk < 8; kk++) {
            const uint32_t kb = (uint32_t)(kk * 32);   // 16 bf16 = 32 bytes
            uint32_t a0[4], a1[4];
            ldmatrix_x4(a0, aBase0 + kb);
            ldmatrix_x4(a1, aBase1 + kb);
#pragma unroll
            for (int jp = 0; jp < 4; jp++) {
                uint32_t bq[4];
                ldmatrix_x4(bq, bAddr[jp] + kb);
                mma16816(acc[0][2 * jp],     a0, bq[0], bq[1]);
                mma16816(acc[1][2 * jp],     a1, bq[0], bq[1]);
                mma16816(acc[0][2 * jp + 1], a0, bq[2], bq[3]);
                mma16816(acc[1][2 * jp + 1], a1, bq[2], bq[3]);
            }
        }

        const int mt = mt0 + lt;
#pragma unroll
        for (int i = 0; i < 2; i++) {
            float rs0 = 0.f, rs1 = 0.f;
#pragma unroll
            for (int j = 0; j < 8; j++) {
                int nl = wn * 64 + j * 8 + 2 * t;
                float bg0 = bg_s[nl], bg1 = bg_s[nl + 1];
                rs0 += __expf(acc[i][j][0] + bg0) + __expf(acc[i][j][1] + bg1);
                rs1 += __expf(acc[i][j][2] + bg0) + __expf(acc[i][j][3] + bg1);
            }
            rs0 += __shfl_xor_sync(0xffffffffu, rs0, 1);
            rs0 += __shfl_xor_sync(0xffffffffu, rs0, 2);
            rs1 += __shfl_xor_sync(0xffffffffu, rs1, 1);
            rs1 += __shfl_xor_sync(0xffffffffu, rs1, 2);
            if (t == 0) {
                int m = mt * 128 + wm * 32 + i * 16 + g;
                atomicAdd(&g_S[m], rs0);
                atomicAdd(&g_S[m + 8], rs1);
            }
        }
        __syncthreads();
    }
#endif
}

// ---------------- kernel 3: final reduction ----------------
__global__ void __launch_bounds__(1024) k_final(float* __restrict__ out) {
    __shared__ float red[1024];
    const int tid = threadIdx.x;
    float a = 0.f;
    for (int i = tid; i < BB_; i += 1024)
        a += g_kl[i] - g_R[i] + (float)CC * __logf(g_S[i]);
    red[tid] = a;
    __syncthreads();
    for (int s = 512; s; s >>= 1) {
        if (tid < s) red[tid] += red[tid + s];
        __syncthreads();
    }
    if (tid == 0) out[0] = red[0] / (float)BB_;
}

// ---------------- launch ----------------
extern "C" void kernel_launch(void* const* d_in, const int* in_sizes, int n_in,
                              void* d_out, int out_size) {
    const int*   x_batch = (const int*)  d_in[0];
    const int*   ctx     = (const int*)  d_in[1];
    const float* eps     = (const float*)d_in[2];
    const float* inf_emb = (const float*)d_in[3];
    const float* W_aff   = (const float*)d_in[4];
    const float* b_aff   = (const float*)d_in[5];
    const float* W_mu    = (const float*)d_in[6];
    const float* b_mu    = (const float*)d_in[7];
    const float* W_sig   = (const float*)d_in[8];
    const float* b_sig   = (const float*)d_in[9];
    const float* gse     = (const float*)d_in[10];
    const float* W_gen   = (const float*)d_in[11];
    const float* b_gen   = (const float*)d_in[12];

    const int SMEM_A = (256 * WT_LD + 176 * 128) * 4;   // 229376 B
    cudaFuncSetAttribute(k_infnet, cudaFuncAttributeMaxDynamicSharedMemorySize, SMEM_A);
    cudaFuncSetAttribute(k_logits, cudaFuncAttributeMaxDynamicSharedMemorySize, SMEM_LOG);

    k_infnet<<<128, 128, SMEM_A>>>(x_batch, ctx, eps, inf_emb, W_aff, b_aff,
                                   W_mu, b_mu, W_sig, b_sig, gse, W_gen, b_gen);
    k_logits<<<dim3(NPAD / 128, 2), 256, SMEM_LOG>>>(W_gen, b_gen);
    k_final<<<1, 1024>>>((float*)d_out);
}

// round 6
// speedup vs baseline: 1.1325x; 1.1325x over previous
#include <cuda_runtime.h>
#include <cuda_bf16.h>
#include <math.h>
#include <stdint.h>

#define NV   50257
#define NPAD 50304          // 393 * 128
#define DD   128
#define BB_  2048
#define CC   10

// Does THIS compilation pass support tcgen05? (sm_103a / sm_100a arch-specific,
// or family-specific). Plain sm_103 pass compiles the mma.sync fallback.
#if defined(__CUDA_ARCH__) && (defined(__CUDA_ARCH_FEAT_SM103_ALL) || \
    defined(__CUDA_ARCH_FEAT_SM100_ALL) || defined(__CUDA_ARCH_FAMILY_SPECIFIC__))
#define HAS_TCGEN05 1
#else
#define HAS_TCGEN05 0
#endif

// ---------------- scratch (static __device__ — allocation-free) ----------------
__device__ __align__(16) __nv_bfloat16 g_zb[BB_ * DD];    // z in bf16
__device__ float g_S[BB_];                                // sum exp(logits) per row
__device__ float g_R[BB_];                                // sum of picked logits per row
__device__ float g_kl[BB_];

// ---------------- common helpers ----------------
__device__ __forceinline__ uint32_t smem_to_u32(const void* p) {
    uint32_t a;
    asm("{ .reg .u64 t; cvta.to.shared.u64 t, %1; cvt.u32.u64 %0, t; }"
        : "=r"(a) : "l"(p));
    return a;
}
__device__ __forceinline__ float softplusf(float x) {
    return fmaxf(x, 0.f) + log1pf(expf(-fabsf(x)));
}

// ---------------- kernel 1: inference network + KL + z + ctx-logits ----------------
// 128 CTAs x 256 threads (8 warps). Warps 0-3 handle e in [0,64), warps 4-7
// e in [64,128) for the SAME 16 batch rows; partial pre-activation sums are
// combined in smem before the ReLU. GEMV: warps 0-3 -> mu, warps 4-7 -> sig,
// with hsum broadcast from smem (no shfl chains).
#define WT_LD 136
__global__ void __launch_bounds__(256) k_infnet(
    const int* __restrict__ x_batch, const int* __restrict__ ctx,
    const float* __restrict__ eps, const float* __restrict__ inf_emb,
    const float* __restrict__ W_aff, const float* __restrict__ b_aff,
    const float* __restrict__ W_mu,  const float* __restrict__ b_mu,
    const float* __restrict__ W_sig, const float* __restrict__ b_sig,
    const float* __restrict__ gen_sigma_emb,
    const float* __restrict__ W_gen, const float* __restrict__ b_gen)
{
    extern __shared__ float sm[];
    float* Wt   = sm;                       // 256*136 floats
    float* embs = sm + 256 * WT_LD;         // 176*128 floats

    const int tid  = threadIdx.x;
    const int w    = tid >> 5;
    const int lane = tid & 31;
    const int wh   = w >> 2;                // e-half: 0 or 1
    const int wl   = w & 3;
    const int e0   = wh * 64;
    const int b0   = blockIdx.x * 16;

    if (tid < 16) { g_S[b0 + tid] = 0.f; g_R[b0 + tid] = 0.f; }

    // stage W_aff transposed: Wt[e][d] = W_aff[d][e]
    for (int idx = tid; idx < 128 * 256; idx += 256) {
        int d = idx >> 8, e = idx & 255;
        Wt[e * WT_LD + d] = W_aff[idx];
    }
    // stage embeddings: row r = b*11 + j ; j==0 -> center, else ctx[j-1]
    for (int r = w; r < 176; r += 8) {
        int b = r / 11, j = r - b * 11;
        int bg = b0 + b;
        int word = (j == 0) ? x_batch[bg] : ctx[bg * CC + (j - 1)];
        const float4* src = (const float4*)(inf_emb + (size_t)word * DD);
        ((float4*)(embs + r * 128))[lane] = src[lane];
    }
    __syncthreads();

    const int d0 = lane * 4;
    float4 ba = *(const float4*)(b_aff + d0);

    int bl[4];
    const float* cbase[4];
#pragma unroll
    for (int bb = 0; bb < 4; bb++) {
        bl[bb] = wl + bb * 4;
        cbase[bb] = embs + (bl[bb] * 11) * 128;
    }

    // s0 partial: this half's 64 e's of (b_aff +) center . W_aff[:, 0:128]
    float s0[4][4];
#pragma unroll
    for (int bb = 0; bb < 4; bb++) {
        if (wh == 0) {
            s0[bb][0] = ba.x; s0[bb][1] = ba.y; s0[bb][2] = ba.z; s0[bb][3] = ba.w;
        } else {
            s0[bb][0] = 0.f; s0[bb][1] = 0.f; s0[bb][2] = 0.f; s0[bb][3] = 0.f;
        }
    }
#pragma unroll 4
    for (int ee = 0; ee < 64; ee++) {
        int e = e0 + ee;
        float4 wv = *(const float4*)(Wt + e * WT_LD + d0);
#pragma unroll
        for (int bb = 0; bb < 4; bb++) {
            float cv = cbase[bb][e];
            s0[bb][0] += cv * wv.x; s0[bb][1] += cv * wv.y;
            s0[bb][2] += cv * wv.z; s0[bb][3] += cv * wv.w;
        }
    }
    __syncthreads();      // center W rows of Wt are now dead -> reuse as redbuf

    float* redbuf = Wt;   // 16 batches x 128 dims (rows 0..15 of Wt region)

    float hsum[4][4];     // valid in wh==0 warps
#pragma unroll
    for (int bb = 0; bb < 4; bb++)
#pragma unroll
        for (int q = 0; q < 4; q++) hsum[bb][q] = 0.f;

    for (int c = 0; c < CC; c++) {
        float ha[4][4];
#pragma unroll
        for (int bb = 0; bb < 4; bb++)
#pragma unroll
            for (int q = 0; q < 4; q++) ha[bb][q] = s0[bb][q];
#pragma unroll 4
        for (int ee = 0; ee < 64; ee++) {
            int e = e0 + ee;
            float4 wv = *(const float4*)(Wt + (128 + e) * WT_LD + d0);
#pragma unroll
            for (int bb = 0; bb < 4; bb++) {
                float cv = cbase[bb][(1 + c) * 128 + e];
                ha[bb][0] += cv * wv.x; ha[bb][1] += cv * wv.y;
                ha[bb][2] += cv * wv.z; ha[bb][3] += cv * wv.w;
            }
        }
        if (wh == 1) {
#pragma unroll
            for (int bb = 0; bb < 4; bb++)
                *(float4*)(redbuf + bl[bb] * 128 + d0) =
                    make_float4(ha[bb][0], ha[bb][1], ha[bb][2], ha[bb][3]);
        }
        __syncthreads();
        if (wh == 0) {
#pragma unroll
            for (int bb = 0; bb < 4; bb++) {
                float4 o4 = *(const float4*)(redbuf + bl[bb] * 128 + d0);
                hsum[bb][0] += fmaxf(ha[bb][0] + o4.x, 0.f);
                hsum[bb][1] += fmaxf(ha[bb][1] + o4.y, 0.f);
                hsum[bb][2] += fmaxf(ha[bb][2] + o4.z, 0.f);
                hsum[bb][3] += fmaxf(ha[bb][3] + o4.w, 0.f);
            }
        }
        __syncthreads();
    }

    // publish hsum; stage W_mu^T (rows 0..127) and W_sig^T (rows 128..255)
    float* hsm = embs;            // 16*128 floats (embs dead after c-loop)
    if (wh == 0) {
#pragma unroll
        for (int bb = 0; bb < 4; bb++)
            *(float4*)(hsm + bl[bb] * 128 + d0) =
                make_float4(hsum[bb][0], hsum[bb][1], hsum[bb][2], hsum[bb][3]);
    }
    for (int idx = tid; idx < 128 * 128; idx += 256) {
        int d = idx >> 7, k = idx & 127;
        Wt[k * WT_LD + d]         = W_mu[idx];
        Wt[(128 + k) * WT_LD + d] = W_sig[idx];
    }
    __syncthreads();

    // GEMV: wh==0 -> mu, wh==1 -> sig (acc[bb][q])
    float4 bias4 = (wh == 0) ? *(const float4*)(b_mu + d0)
                             : *(const float4*)(b_sig + d0);
    float acc[4][4];
#pragma unroll
    for (int bb = 0; bb < 4; bb++) {
        acc[bb][0] = bias4.x; acc[bb][1] = bias4.y;
        acc[bb][2] = bias4.z; acc[bb][3] = bias4.w;
    }
    const int krow0 = wh * 128;
#pragma unroll 4
    for (int k = 0; k < 128; k++) {
        float4 w4 = *(const float4*)(Wt + (krow0 + k) * WT_LD + d0);
#pragma unroll
        for (int bb = 0; bb < 4; bb++) {
            float hv = hsm[bl[bb] * 128 + k];
            acc[bb][0] += hv * w4.x; acc[bb][1] += hv * w4.y;
            acc[bb][2] += hv * w4.z; acc[bb][3] += hv * w4.w;
        }
    }

    // sig half publishes; mu half does the epilogue
    float* sgb = embs + 2048;     // 16*128 floats
    if (wh == 1) {
#pragma unroll
        for (int bb = 0; bb < 4; bb++)
            *(float4*)(sgb + bl[bb] * 128 + d0) =
                make_float4(acc[bb][0], acc[bb][1], acc[bb][2], acc[bb][3]);
    }
    __syncthreads();

    float* zsm = Wt;              // reuse again: 16*128 z values
    if (wh == 0) {
#pragma unroll
        for (int bb = 0; bb < 4; bb++) {
            int bg = b0 + bl[bb];
            int xb = x_batch[bg];
            float4 sg4 = *(const float4*)(sgb + bl[bb] * 128 + d0);
            float4 ep4 = *(const float4*)(eps + (size_t)bg * DD + d0);
            float4 gs4 = *(const float4*)(gen_sigma_emb + (size_t)xb * DD + d0);
            float sgv[4] = {sg4.x, sg4.y, sg4.z, sg4.w};
            float epv[4] = {ep4.x, ep4.y, ep4.z, ep4.w};
            float gsv[4] = {gs4.x, gs4.y, gs4.z, gs4.w};
            float zq[4];
            float klacc = 0.f;
#pragma unroll
            for (int q = 0; q < 4; q++) {
                float m   = acc[bb][q];
                float isg = softplusf(sgv[q]);
                float zv  = m + epv[q] * isg;
                zq[q] = zv;
                float sgm = softplusf(gsv[q]);
                float dm  = m - sgm;
                klacc += logf(sgm / isg)
                       + (isg * isg + dm * dm) / (2.f * sgm * sgm) - 0.5f;
            }
            *(float4*)(zsm + bl[bb] * 128 + d0) = make_float4(zq[0], zq[1], zq[2], zq[3]);
            __nv_bfloat162 p0 = __floats2bfloat162_rn(zq[0], zq[1]);
            __nv_bfloat162 p1 = __floats2bfloat162_rn(zq[2], zq[3]);
            ((__nv_bfloat162*)(g_zb + (size_t)bg * DD + d0))[0] = p0;
            ((__nv_bfloat162*)(g_zb + (size_t)bg * DD + d0))[1] = p1;
#pragma unroll
            for (int o = 16; o; o >>= 1) klacc += __shfl_xor_sync(0xffffffffu, klacc, o);
            if (lane == 0) g_kl[bg] = klacc;
        }
    }
    __syncthreads();

    // ---- picked context logits (fp32): 160 (b,c) pairs over 8 warps ----
    for (int pp = w; pp < 16 * CC; pp += 8) {
        int b = pp / CC, c = pp - b * CC;
        int bg = b0 + b;
        int n  = ctx[bg * CC + c];
        float4 w4 = ((const float4*)(W_gen + (size_t)n * DD))[lane];
        float4 z4 = *(const float4*)(zsm + b * 128 + d0);
        float d = z4.x * w4.x + z4.y * w4.y + z4.z * w4.z + z4.w * w4.w;
#pragma unroll
        for (int o = 16; o; o >>= 1) d += __shfl_xor_sync(0xffffffffu, d, o);
        if (lane == 0) atomicAdd(&g_R[bg], d + b_gen[n]);
    }
}

// ======================== k_logits: two arch paths ========================
// grid = (393, 2): blockIdx.x = vocab tile (N=128), blockIdx.y picks 8 of the
// 16 batch tiles -> 786 uniform CTAs = balanced 3 rounds at 2 CTA/SM.
#define MT_PER_CTA 8

#if HAS_TCGEN05
__device__ __forceinline__ uint32_t elect_one_pred() {
    uint32_t pred;
    asm volatile(
        "{\n\t.reg .pred p;\n\t"
        "elect.sync _|p, 0xFFFFFFFF;\n\t"
        "selp.b32 %0, 1, 0, p;\n\t}"
        : "=r"(pred));
    return pred;
}
#define MBARRIER_INIT(mbar, cnt) \
    asm volatile("mbarrier.init.shared.b64 [%0], %1;" :: "r"((uint32_t)(mbar)), "r"((uint32_t)(cnt)) : "memory")
#define MBARRIER_WAIT_PARITY(mbar, par) do { \
    uint32_t _m = (uint32_t)(mbar); uint32_t _p = (uint32_t)(par); uint32_t _d; \
    asm volatile("{\n\t.reg .pred p;\n\t" \
        "mbarrier.try_wait.parity.acquire.cta.shared::cta.b64 p, [%1], %2;\n\t" \
        "selp.b32 %0, 1, 0, p;\n\t}" : "=r"(_d) : "r"(_m), "r"(_p) : "memory"); \
    if (!_d) { \
        asm volatile("{\n\t.reg .pred P1;\n\t" \
            "WL_%=:\n\t" \
            "mbarrier.try_wait.parity.acquire.cta.shared::cta.b64 P1, [%0], %1, 0x989680;\n\t" \
            "@P1 bra.uni WD_%=;\n\t" \
            "bra.uni WL_%=;\n\t" \
            "WD_%=:\n\t}" :: "r"(_m), "r"(_p) : "memory"); \
    } } while (0)
#define TCGEN05_ALLOC(smem_addr, nCols) \
    asm volatile("tcgen05.alloc.cta_group::1.sync.aligned.shared::cta.b32 [%0], %1;" \
        :: "r"((uint32_t)(smem_addr)), "r"((uint32_t)(nCols)) : "memory")
#define TCGEN05_DEALLOC(tmem, nCols) \
    asm volatile("tcgen05.dealloc.cta_group::1.sync.aligned.b32 %0, %1;" :: "r"(tmem), "r"((uint32_t)(nCols)))
#define TCGEN05_RELINQUISH() \
    asm volatile("tcgen05.relinquish_alloc_permit.cta_group::1.sync.aligned;")
#define TCGEN05_COMMIT(mbar) \
    asm volatile("tcgen05.commit.cta_group::1.mbarrier::arrive::one.shared::cluster.b64 [%0];" \
        :: "r"((uint32_t)(mbar)) : "memory")
#define TCGEN05_FENCE_BEFORE() asm volatile("tcgen05.fence::before_thread_sync;" ::: "memory")
#define TCGEN05_FENCE_AFTER()  asm volatile("tcgen05.fence::after_thread_sync;" ::: "memory")
#define TCGEN05_WAIT_LD()      asm volatile("tcgen05.wait::ld.sync.aligned;" ::: "memory")
#define FENCE_PROXY_ASYNC()    asm volatile("fence.proxy.async.shared::cta;" ::: "memory")
#define TCGEN05_LD_32X32B_X32(r, tmem_addr) \
    asm volatile( \
        "tcgen05.ld.sync.aligned.32x32b.x32.b32 " \
        "{%0, %1, %2, %3, %4, %5, %6, %7, " \
        " %8, %9, %10, %11, %12, %13, %14, %15, " \
        " %16, %17, %18, %19, %20, %21, %22, %23, " \
        " %24, %25, %26, %27, %28, %29, %30, %31}, [%32];" \
        : "=r"((r)[0]),  "=r"((r)[1]),  "=r"((r)[2]),  "=r"((r)[3]), \
          "=r"((r)[4]),  "=r"((r)[5]),  "=r"((r)[6]),  "=r"((r)[7]), \
          "=r"((r)[8]),  "=r"((r)[9]),  "=r"((r)[10]), "=r"((r)[11]), \
          "=r"((r)[12]), "=r"((r)[13]), "=r"((r)[14]), "=r"((r)[15]), \
          "=r"((r)[16]), "=r"((r)[17]), "=r"((r)[18]), "=r"((r)[19]), \
          "=r"((r)[20]), "=r"((r)[21]), "=r"((r)[22]), "=r"((r)[23]), \
          "=r"((r)[24]), "=r"((r)[25]), "=r"((r)[26]), "=r"((r)[27]), \
          "=r"((r)[28]), "=r"((r)[29]), "=r"((r)[30]), "=r"((r)[31]) \
        : "r"(tmem_addr))
static constexpr uint64_t SMEM_DESC_BASE_SW128 =
    (uint64_t(2) << 61) | (uint64_t(1) << 46) | (uint64_t(64) << 32) | (uint64_t(1) << 16);
#define MAKE_SMEM_DESC(addr) (SMEM_DESC_BASE_SW128 | ((uint64_t)((addr) >> 4) & 0x3FFF))
#define IDESC_LOG 0x08200490u   // f32 accum, bf16 x bf16, M=128, N=128

__device__ __forceinline__ void mma_f16_ss(uint32_t d_tmem, uint64_t a_desc,
                                           uint64_t b_desc, uint32_t idesc, bool accum) {
    uint32_t en = accum ? 1u : 0u;
    asm volatile(
        "{\n\t.reg .pred p;\n\t"
        "setp.ne.u32 p, %4, 0;\n\t"
        "tcgen05.mma.cta_group::1.kind::f16 [%0], %1, %2, %3, {%5,%5,%5,%5}, p;\n\t}"
        :: "r"(d_tmem), "l"(a_desc), "l"(b_desc), "r"(idesc), "r"(en), "r"(0u)
        : "memory");
}

#define SM_TPTR  0
#define SM_MBAR0 8
#define SM_MBAR1 16
#define SM_BG    32
#define SM_W     1024
#define SM_Z0    (1024 + 32768)
#define SM_Z1    (1024 + 65536)

__device__ __forceinline__ void logits_epilogue(int lt, int mt, uint32_t sb, uint32_t tmem,
                                                const float* bg_s, int w, int lane) {
    const int q = lt & 1;
    MBARRIER_WAIT_PARITY(sb + (q ? SM_MBAR1 : SM_MBAR0), (lt >> 1) & 1);
    TCGEN05_FENCE_AFTER();
    const uint32_t woff = ((uint32_t)(w & 3)) << 21;
    const int cb = (w < 4) ? 0 : 64;
    const uint32_t dt = tmem + (uint32_t)(q * 128 + cb) + woff;
    uint32_t r0[32], r1[32];
    TCGEN05_LD_32X32B_X32(r0, dt);
    TCGEN05_LD_32X32B_X32(r1, dt + 32);
    TCGEN05_WAIT_LD();
    TCGEN05_FENCE_BEFORE();
    float acc = 0.f;
#pragma unroll
    for (int c = 0; c < 32; c++) acc += __expf(__uint_as_float(r0[c]) + bg_s[cb + c]);
#pragma unroll
    for (int c = 0; c < 32; c++) acc += __expf(__uint_as_float(r1[c]) + bg_s[cb + 32 + c]);
    atomicAdd(&g_S[mt * 128 + (w & 3) * 32 + lane], acc);
}
#endif  // HAS_TCGEN05

// ---- fallback helpers (baseline sm_103: mma.sync + ldmatrix + cp.async) ----
__device__ __forceinline__ void mma16816(float c[4], const uint32_t a[4],
                                         uint32_t b0, uint32_t b1) {
    asm volatile(
        "mma.sync.aligned.m16n8k16.row.col.f32.bf16.bf16.f32 "
        "{%0,%1,%2,%3},{%4,%5,%6,%7},{%8,%9},{%0,%1,%2,%3};\n"
        : "+f"(c[0]), "+f"(c[1]), "+f"(c[2]), "+f"(c[3])
        : "r"(a[0]), "r"(a[1]), "r"(a[2]), "r"(a[3]), "r"(b0), "r"(b1));
}
__device__ __forceinline__ void ldmatrix_x4(uint32_t r[4], uint32_t addr) {
    asm volatile("ldmatrix.sync.aligned.m8n8.x4.shared.b16 {%0,%1,%2,%3}, [%4];"
        : "=r"(r[0]), "=r"(r[1]), "=r"(r[2]), "=r"(r[3]) : "r"(addr));
}
#define CP_ASYNC16(dst, src) \
    asm volatile("cp.async.cg.shared.global [%0], [%1], 16;" :: "r"(dst), "l"(src))
#define CP_COMMIT()  asm volatile("cp.async.commit_group;" ::: "memory")
#define CP_WAIT(n)   asm volatile("cp.async.wait_group %0;" :: "n"(n) : "memory")

#define TLD    136
#define FB_WS  69632
#define FB_BG  104448
#define SMEM_LOG 104960   // covers both paths (tcgen05 path needs 99328)

__device__ __forceinline__ void fb_prefetch(uint32_t sb, int mt, int p, int tid) {
#pragma unroll
    for (int idx = tid; idx < 2048; idx += 256) {
        int r = idx >> 4, c = idx & 15;
        uint32_t dst = sb + (uint32_t)(p * 34816 + (r * TLD + c * 8) * 2);
        const void* src = (const void*)(g_zb + (size_t)(mt * 128 + r) * DD + c * 8);
        CP_ASYNC16(dst, src);
    }
    CP_COMMIT();
}

__global__ void __launch_bounds__(256, 2) k_logits(const float* __restrict__ W_gen,
                                                   const float* __restrict__ b_gen) {
#if HAS_TCGEN05
    // ---------------- tcgen05 path ----------------
    extern __shared__ __align__(16) char smem[];
    const uint32_t sb = smem_to_u32(smem);
    const int tid  = threadIdx.x;
    const int w    = tid >> 5;
    const int lane = tid & 31;
    const int n0   = blockIdx.x * 128;
    const int mt0  = blockIdx.y * MT_PER_CTA;

    if (w == 0) { TCGEN05_ALLOC(sb + SM_TPTR, 256); TCGEN05_RELINQUISH(); }
    if (tid == 0) { MBARRIER_INIT(sb + SM_MBAR0, 1); MBARRIER_INIT(sb + SM_MBAR1, 1); }

    for (int gidx = tid; gidx < 2048; gidx += 256) {
        int r  = gidx >> 4;
        int g8 = gidx & 15;
        int n  = n0 + r;
        uint4 outv = make_uint4(0u, 0u, 0u, 0u);
        if (n < NV) {
            const float4* src = (const float4*)(W_gen + (size_t)n * DD + g8 * 8);
            float4 f0 = src[0], f1 = src[1];
            __nv_bfloat162 h0 = __floats2bfloat162_rn(f0.x, f0.y);
            __nv_bfloat162 h1 = __floats2bfloat162_rn(f0.z, f0.w);
            __nv_bfloat162 h2 = __floats2bfloat162_rn(f1.x, f1.y);
            __nv_bfloat162 h3 = __floats2bfloat162_rn(f1.z, f1.w);
            outv.x = *(uint32_t*)&h0; outv.y = *(uint32_t*)&h1;
            outv.z = *(uint32_t*)&h2; outv.w = *(uint32_t*)&h3;
        }
        int half = g8 >> 3;
        uint32_t boff = (uint32_t)(r * 128 + (g8 & 7) * 16);
        uint32_t sw = boff ^ ((boff >> 3) & 0x70);
        *(uint4*)(smem + SM_W + half * 16384 + sw) = outv;
    }
    if (tid < 128) {
        int n = n0 + tid;
        ((float*)(smem + SM_BG))[tid] = (n < NV) ? b_gen[n] : -88.0f;
    }
    FENCE_PROXY_ASYNC();
    __syncthreads();

    uint32_t tmem;
    asm volatile("ld.shared.b32 %0, [%1];" : "=r"(tmem) : "r"(sb + SM_TPTR));
    const float* bg_s = (const float*)(smem + SM_BG);

    const uint64_t bd0 = MAKE_SMEM_DESC(sb + SM_W);
    const uint64_t bd1 = MAKE_SMEM_DESC(sb + SM_W + 16384);

    for (int lt = 0; lt < MT_PER_CTA; lt++) {
        const int mt = mt0 + lt;
        const int p = lt & 1, k = lt >> 1;
        const uint32_t zoff = p ? SM_Z1 : SM_Z0;
        if (lt >= 2) MBARRIER_WAIT_PARITY(sb + (p ? SM_MBAR1 : SM_MBAR0), (k - 1) & 1);
        for (int gidx = tid; gidx < 2048; gidx += 256) {
            int r = gidx >> 4, g8 = gidx & 15;
            uint4 val = *(const uint4*)(g_zb + ((size_t)(mt * 128 + r)) * DD + g8 * 8);
            int half = g8 >> 3;
            uint32_t boff = (uint32_t)(r * 128 + (g8 & 7) * 16);
            uint32_t sw = boff ^ ((boff >> 3) & 0x70);
            *(uint4*)(smem + zoff + half * 16384 + sw) = val;
        }
        FENCE_PROXY_ASYNC();
        __syncthreads();
        if (w == 0) {
            TCGEN05_FENCE_AFTER();
            if (elect_one_pred()) {
                const uint64_t ad0 = MAKE_SMEM_DESC(sb + zoff);
                const uint64_t ad1 = MAKE_SMEM_DESC(sb + zoff + 16384);
                const uint32_t dt = tmem + (uint32_t)(p * 128);
#pragma unroll
                for (int s = 0; s < 8; s++) {
                    uint64_t ad = ((s >> 2) ? ad1 : ad0) + (uint64_t)((s & 3) * 2);
                    uint64_t bd = ((s >> 2) ? bd1 : bd0) + (uint64_t)((s & 3) * 2);
                    mma_f16_ss(dt, ad, bd, IDESC_LOG, s > 0);
                }
                TCGEN05_COMMIT(sb + (p ? SM_MBAR1 : SM_MBAR0));
            }
        }
        if (lt >= 1) logits_epilogue(lt - 1, mt - 1, sb, tmem, bg_s, w, lane);
    }
    logits_epilogue(MT_PER_CTA - 1, mt0 + MT_PER_CTA - 1, sb, tmem, bg_s, w, lane);
    __syncthreads();
    if (w == 0) TCGEN05_DEALLOC(tmem, 256);
#else
    // ---------------- fallback: mma.sync + ldmatrix + cp.async double buffer ----
    extern __shared__ __align__(16) char smem[];
    const uint32_t sb = smem_to_u32(smem);
    __nv_bfloat16* Ws = (__nv_bfloat16*)(smem + FB_WS);
    float* bg_s = (float*)(smem + FB_BG);

    const int tid = threadIdx.x;
    const int n0  = blockIdx.x * 128;
    const int mt0 = blockIdx.y * MT_PER_CTA;

    for (int gidx = tid; gidx < 2048; gidx += 256) {
        int r = gidx >> 4, c = gidx & 15;
        int n = n0 + r;
        uint4 outv = make_uint4(0u, 0u, 0u, 0u);
        if (n < NV) {
            const float4* src = (const float4*)(W_gen + (size_t)n * DD + c * 8);
            float4 f0 = src[0], f1 = src[1];
            __nv_bfloat162 h0 = __floats2bfloat162_rn(f0.x, f0.y);
            __nv_bfloat162 h1 = __floats2bfloat162_rn(f0.z, f0.w);
            __nv_bfloat162 h2 = __floats2bfloat162_rn(f1.x, f1.y);
            __nv_bfloat162 h3 = __floats2bfloat162_rn(f1.z, f1.w);
            outv.x = *(uint32_t*)&h0; outv.y = *(uint32_t*)&h1;
            outv.z = *(uint32_t*)&h2; outv.w = *(uint32_t*)&h3;
        }
        *(uint4*)(Ws + r * TLD + c * 8) = outv;
    }
    if (tid < 128) {
        int n = n0 + tid;
        bg_s[tid] = (n < NV) ? b_gen[n] : -88.0f;
    }

    const int w    = tid >> 5;
    const int lane = tid & 31;
    const int g    = lane >> 2;
    const int t    = lane & 3;
    const int wm   = w & 3;
    const int wn   = w >> 2;

    const uint32_t aLane = (uint32_t)(((wm * 32 + (lane & 15)) * TLD + ((lane & 16) >> 1)) * 2);
    uint32_t bAddr[4];
#pragma unroll
    for (int jp = 0; jp < 4; jp++)
        bAddr[jp] = sb + FB_WS +
            (uint32_t)(((wn * 64 + jp * 16 + ((lane & 16) >> 1) + (lane & 7)) * TLD + (lane & 8)) * 2);

    fb_prefetch(sb, mt0, 0, tid);

    for (int lt = 0; lt < MT_PER_CTA; lt++) {
        const int p = lt & 1;
        if (lt + 1 < MT_PER_CTA) { fb_prefetch(sb, mt0 + lt + 1, p ^ 1, tid); CP_WAIT(1); }
        else                     { CP_WAIT(0); }
        __syncthreads();
        const uint32_t aBase0 = sb + (uint32_t)(p * 34816) + aLane;
        const uint32_t aBase1 = aBase0 + (uint32_t)(16 * TLD * 2);

        float acc[2][8][4];
#pragma unroll
        for (int i = 0; i < 2; i++)
#pragma unroll
            for (int j = 0; j < 8; j++)
#pragma unroll
                for (int q = 0; q < 4; q++) acc[i][j][q] = 0.f;

#pragma unroll
        for (int kk = 0; kk < 8; kk++) {
            const uint32_t kb = (uint32_t)(kk * 32);
            uint32_t a0[4], a1[4];
            ldmatrix_x4(a0, aBase0 + kb);
            ldmatrix_x4(a1, aBase1 + kb);
#pragma unroll
            for (int jp = 0; jp < 4; jp++) {
                uint32_t bq[4];
                ldmatrix_x4(bq, bAddr[jp] + kb);
                mma16816(acc[0][2 * jp],     a0, bq[0], bq[1]);
                mma16816(acc[1][2 * jp],     a1, bq[0], bq[1]);
                mma16816(acc[0][2 * jp + 1], a0, bq[2], bq[3]);
                mma16816(acc[1][2 * jp + 1], a1, bq[2], bq[3]);
            }
        }

        const int mt = mt0 + lt;
#pragma unroll
        for (int i = 0; i < 2; i++) {
            float rs0 = 0.f, rs1 = 0.f;
#pragma unroll
            for (int j = 0; j < 8; j++) {
                int nl = wn * 64 + j * 8 + 2 * t;
                float bg0 = bg_s[nl], bg1 = bg_s[nl + 1];
                rs0 += __expf(acc[i][j][0] + bg0) + __expf(acc[i][j][1] + bg1);
                rs1 += __expf(acc[i][j][2] + bg0) + __expf(acc[i][j][3] + bg1);
            }
            rs0 += __shfl_xor_sync(0xffffffffu, rs0, 1);
            rs0 += __shfl_xor_sync(0xffffffffu, rs0, 2);
            rs1 += __shfl_xor_sync(0xffffffffu, rs1, 1);
            rs1 += __shfl_xor_sync(0xffffffffu, rs1, 2);
            if (t == 0) {
                int m = mt * 128 + wm * 32 + i * 16 + g;
                atomicAdd(&g_S[m], rs0);
                atomicAdd(&g_S[m + 8], rs1);
            }
        }
        __syncthreads();
    }
#endif
}

// ---------------- kernel 3: final reduction ----------------
__global__ void __launch_bounds__(1024) k_final(float* __restrict__ out) {
    __shared__ float red[1024];
    const int tid = threadIdx.x;
    float a = 0.f;
    for (int i = tid; i < BB_; i += 1024)
        a += g_kl[i] - g_R[i] + (float)CC * __logf(g_S[i]);
    red[tid] = a;
    __syncthreads();
    for (int s = 512; s; s >>= 1) {
        if (tid < s) red[tid] += red[tid + s];
        __syncthreads();
    }
    if (tid == 0) out[0] = red[0] / (float)BB_;
}

// ---------------- launch ----------------
extern "C" void kernel_launch(void* const* d_in, const int* in_sizes, int n_in,
                              void* d_out, int out_size) {
    const int*   x_batch = (const int*)  d_in[0];
    const int*   ctx     = (const int*)  d_in[1];
    const float* eps     = (const float*)d_in[2];
    const float* inf_emb = (const float*)d_in[3];
    const float* W_aff   = (const float*)d_in[4];
    const float* b_aff   = (const float*)d_in[5];
    const float* W_mu    = (const float*)d_in[6];
    const float* b_mu    = (const float*)d_in[7];
    const float* W_sig   = (const float*)d_in[8];
    const float* b_sig   = (const float*)d_in[9];
    const float* gse     = (const float*)d_in[10];
    const float* W_gen   = (const float*)d_in[11];
    const float* b_gen   = (const float*)d_in[12];

    const int SMEM_A = (256 * WT_LD + 176 * 128) * 4;   // 229376 B
    cudaFuncSetAttribute(k_infnet, cudaFuncAttributeMaxDynamicSharedMemorySize, SMEM_A);
    cudaFuncSetAttribute(k_logits, cudaFuncAttributeMaxDynamicSharedMemorySize, SMEM_LOG);

    k_infnet<<<128, 256, SMEM_A>>>(x_batch, ctx, eps, inf_emb, W_aff, b_aff,
                                   W_mu, b_mu, W_sig, b_sig, gse, W_gen, b_gen);
    k_logits<<<dim3(NPAD / 128, 2), 256, SMEM_LOG>>>(W_gen, b_gen);
    k_final<<<1, 1024>>>((float*)d_out);
}

// round 7
// speedup vs baseline: 1.1449x; 1.0109x over previous
#include <cuda_runtime.h>
#include <cuda_bf16.h>
#include <math.h>
#include <stdint.h>

#define NV   50257
#define NPAD 50304          // 393 * 128
#define DD   128
#define BB_  2048
#define CC   10

// Does THIS compilation pass support tcgen05? (sm_103a / sm_100a arch-specific,
// or family-specific). Plain sm_103 pass compiles the mma.sync fallback.
#if defined(__CUDA_ARCH__) && (defined(__CUDA_ARCH_FEAT_SM103_ALL) || \
    defined(__CUDA_ARCH_FEAT_SM100_ALL) || defined(__CUDA_ARCH_FAMILY_SPECIFIC__))
#define HAS_TCGEN05 1
#else
#define HAS_TCGEN05 0
#endif

typedef unsigned long long u64;

// ---------------- scratch (static __device__ — allocation-free) ----------------
__device__ __align__(16) __nv_bfloat16 g_zb[BB_ * DD];    // z in bf16
__device__ float g_S[BB_];                                // sum exp(logits) per row
__device__ float g_R[BB_];                                // sum of picked logits per row
__device__ float g_kl[BB_];

// ---------------- common helpers ----------------
__device__ __forceinline__ uint32_t smem_to_u32(const void* p) {
    uint32_t a;
    asm("{ .reg .u64 t; cvta.to.shared.u64 t, %1; cvt.u32.u64 %0, t; }"
        : "=r"(a) : "l"(p));
    return a;
}
__device__ __forceinline__ float softplusf(float x) {
    return fmaxf(x, 0.f) + log1pf(expf(-fabsf(x)));
}
// ---- packed fp32x2 (Blackwell baseline sm_100+) ----
__device__ __forceinline__ void fma2(u64& d, u64 a, u64 b) {
    asm("fma.rn.f32x2 %0, %1, %2, %0;" : "+l"(d) : "l"(a), "l"(b));
}
__device__ __forceinline__ u64 pack2(float x) {
    u64 r; asm("mov.b64 %0, {%1, %1};" : "=l"(r) : "f"(x)); return r;
}
__device__ __forceinline__ u64 packxy(float x, float y) {
    u64 r; asm("mov.b64 %0, {%1, %2};" : "=l"(r) : "f"(x), "f"(y)); return r;
}
__device__ __forceinline__ void unpack2(float& lo, float& hi, u64 v) {
    asm("mov.b64 {%0, %1}, %2;" : "=f"(lo), "=f"(hi) : "l"(v));
}

// ---------------- kernel 1: inference network + KL + z + ctx-logits ----------------
// 128 CTAs x 256 threads (8 warps). Warp wl = w&3 owns 4 batches; half wh = w>>2
// owns contexts [wh*5, wh*5+5) with FULL 128-e dots (no in-loop reduction).
// Inner math uses fma.rn.f32x2 (d-pairs packed) — half the FMA-pipe instructions.
#define WT_LD 136
__global__ void __launch_bounds__(256) k_infnet(
    const int* __restrict__ x_batch, const int* __restrict__ ctx,
    const float* __restrict__ eps, const float* __restrict__ inf_emb,
    const float* __restrict__ W_aff, const float* __restrict__ b_aff,
    const float* __restrict__ W_mu,  const float* __restrict__ b_mu,
    const float* __restrict__ W_sig, const float* __restrict__ b_sig,
    const float* __restrict__ gen_sigma_emb,
    const float* __restrict__ W_gen, const float* __restrict__ b_gen)
{
    extern __shared__ float sm[];
    float* Wt   = sm;                       // 256*136 floats
    float* embs = sm + 256 * WT_LD;         // 176*128 floats

    const int tid  = threadIdx.x;
    const int w    = tid >> 5;
    const int lane = tid & 31;
    const int wh   = w >> 2;                // context half
    const int wl   = w & 3;
    const int b0   = blockIdx.x * 16;

    if (tid < 16) { g_S[b0 + tid] = 0.f; g_R[b0 + tid] = 0.f; }

    // stage W_aff transposed: Wt[e][d] = W_aff[d][e]
    for (int idx = tid; idx < 128 * 256; idx += 256) {
        int d = idx >> 8, e = idx & 255;
        Wt[e * WT_LD + d] = W_aff[idx];
    }
    // stage embeddings: row r = b*11 + j ; j==0 -> center, else ctx[j-1]
    for (int r = w; r < 176; r += 8) {
        int b = r / 11, j = r - b * 11;
        int bg = b0 + b;
        int word = (j == 0) ? x_batch[bg] : ctx[bg * CC + (j - 1)];
        const float4* src = (const float4*)(inf_emb + (size_t)word * DD);
        ((float4*)(embs + r * 128))[lane] = src[lane];
    }
    __syncthreads();

    const int d0 = lane * 4;
    float4 ba = *(const float4*)(b_aff + d0);

    int bl[4];
#pragma unroll
    for (int bb = 0; bb < 4; bb++) bl[bb] = wl + bb * 4;

    // ---- s0 = b_aff + center . W_aff[:,0:128]  (full 128 e, both halves) ----
    u64 s2[4][2];
#pragma unroll
    for (int bb = 0; bb < 4; bb++) {
        s2[bb][0] = packxy(ba.x, ba.y);
        s2[bb][1] = packxy(ba.z, ba.w);
    }
    for (int e4 = 0; e4 < 128; e4 += 4) {
        float cv[4][4];
#pragma unroll
        for (int bb = 0; bb < 4; bb++)
            *(float4*)cv[bb] = *(const float4*)(embs + (bl[bb] * 11) * 128 + e4);
#pragma unroll
        for (int q = 0; q < 4; q++) {
            ulonglong2 wv = *(const ulonglong2*)(Wt + (e4 + q) * WT_LD + d0);
#pragma unroll
            for (int bb = 0; bb < 4; bb++) {
                u64 c2 = pack2(cv[bb][q]);
                fma2(s2[bb][0], c2, wv.x);
                fma2(s2[bb][1], c2, wv.y);
            }
        }
    }

    // ---- context loop: this half's 5 contexts, full e, no barriers ----
    float hsum[4][4];
#pragma unroll
    for (int bb = 0; bb < 4; bb++)
#pragma unroll
        for (int q = 0; q < 4; q++) hsum[bb][q] = 0.f;

    const int c0 = wh * 5;
    for (int c = 0; c < 5; c++) {
        u64 h2[4][2];
#pragma unroll
        for (int bb = 0; bb < 4; bb++) { h2[bb][0] = s2[bb][0]; h2[bb][1] = s2[bb][1]; }
        const int crow = 1 + c0 + c;
        for (int e4 = 0; e4 < 128; e4 += 4) {
            float cv[4][4];
#pragma unroll
            for (int bb = 0; bb < 4; bb++)
                *(float4*)cv[bb] = *(const float4*)(embs + (bl[bb] * 11 + crow) * 128 + e4);
#pragma unroll
            for (int q = 0; q < 4; q++) {
                ulonglong2 wv = *(const ulonglong2*)(Wt + (128 + e4 + q) * WT_LD + d0);
#pragma unroll
                for (int bb = 0; bb < 4; bb++) {
                    u64 c2 = pack2(cv[bb][q]);
                    fma2(h2[bb][0], c2, wv.x);
                    fma2(h2[bb][1], c2, wv.y);
                }
            }
        }
#pragma unroll
        for (int bb = 0; bb < 4; bb++) {
            float v0, v1, v2, v3;
            unpack2(v0, v1, h2[bb][0]);
            unpack2(v2, v3, h2[bb][1]);
            hsum[bb][0] += fmaxf(v0, 0.f);
            hsum[bb][1] += fmaxf(v1, 0.f);
            hsum[bb][2] += fmaxf(v2, 0.f);
            hsum[bb][3] += fmaxf(v3, 0.f);
        }
    }
    __syncthreads();   // all warps done reading Wt (W_aff) and embs ctx rows

    // dead-row reuse inside embs:
    //   trow(b) = row b*11   (center, dead)  : wh1 hsum transfer
    //   hrow(b) = row b*11+1 (ctx0, dead)    : combined hsum
    //   srow(b) = row b*11+2 (ctx1, dead)    : sigma pre-activation
    //   zrow(b) = row b*11+3 (ctx2, dead)    : z values
    if (wh == 1) {
#pragma unroll
        for (int bb = 0; bb < 4; bb++)
            *(float4*)(embs + (bl[bb] * 11) * 128 + d0) =
                make_float4(hsum[bb][0], hsum[bb][1], hsum[bb][2], hsum[bb][3]);
    }
    // stage W_mu^T (rows 0..127) and W_sig^T (rows 128..255) into Wt
    for (int idx = tid; idx < 128 * 128; idx += 256) {
        int d = idx >> 7, k = idx & 127;
        Wt[k * WT_LD + d]         = W_mu[idx];
        Wt[(128 + k) * WT_LD + d] = W_sig[idx];
    }
    __syncthreads();

    if (wh == 0) {
#pragma unroll
        for (int bb = 0; bb < 4; bb++) {
            float4 o4 = *(const float4*)(embs + (bl[bb] * 11) * 128 + d0);
            *(float4*)(embs + (bl[bb] * 11 + 1) * 128 + d0) =
                make_float4(hsum[bb][0] + o4.x, hsum[bb][1] + o4.y,
                            hsum[bb][2] + o4.z, hsum[bb][3] + o4.w);
        }
    }
    __syncthreads();

    // ---- GEMV: wh==0 -> mu, wh==1 -> sig, packed fp32x2 ----
    float4 bias4 = (wh == 0) ? *(const float4*)(b_mu + d0)
                             : *(const float4*)(b_sig + d0);
    u64 a2[4][2];
#pragma unroll
    for (int bb = 0; bb < 4; bb++) {
        a2[bb][0] = packxy(bias4.x, bias4.y);
        a2[bb][1] = packxy(bias4.z, bias4.w);
    }
    const int krow0 = wh * 128;
    for (int k4 = 0; k4 < 128; k4 += 4) {
        float hv[4][4];
#pragma unroll
        for (int bb = 0; bb < 4; bb++)
            *(float4*)hv[bb] = *(const float4*)(embs + (bl[bb] * 11 + 1) * 128 + k4);
#pragma unroll
        for (int q = 0; q < 4; q++) {
            ulonglong2 w2 = *(const ulonglong2*)(Wt + (krow0 + k4 + q) * WT_LD + d0);
#pragma unroll
            for (int bb = 0; bb < 4; bb++) {
                u64 h2p = pack2(hv[bb][q]);
                fma2(a2[bb][0], h2p, w2.x);
                fma2(a2[bb][1], h2p, w2.y);
            }
        }
    }
    float acc[4][4];
#pragma unroll
    for (int bb = 0; bb < 4; bb++) {
        unpack2(acc[bb][0], acc[bb][1], a2[bb][0]);
        unpack2(acc[bb][2], acc[bb][3], a2[bb][1]);
    }

    if (wh == 1) {
#pragma unroll
        for (int bb = 0; bb < 4; bb++)
            *(float4*)(embs + (bl[bb] * 11 + 2) * 128 + d0) =
                make_float4(acc[bb][0], acc[bb][1], acc[bb][2], acc[bb][3]);
    }
    __syncthreads();

    if (wh == 0) {
#pragma unroll
        for (int bb = 0; bb < 4; bb++) {
            int bg = b0 + bl[bb];
            int xb = x_batch[bg];
            float4 sg4 = *(const float4*)(embs + (bl[bb] * 11 + 2) * 128 + d0);
            float4 ep4 = *(const float4*)(eps + (size_t)bg * DD + d0);
            float4 gs4 = *(const float4*)(gen_sigma_emb + (size_t)xb * DD + d0);
            float sgv[4] = {sg4.x, sg4.y, sg4.z, sg4.w};
            float epv[4] = {ep4.x, ep4.y, ep4.z, ep4.w};
            float gsv[4] = {gs4.x, gs4.y, gs4.z, gs4.w};
            float zq[4];
            float klacc = 0.f;
#pragma unroll
            for (int q = 0; q < 4; q++) {
                float m   = acc[bb][q];
                float isg = softplusf(sgv[q]);
                float zv  = m + epv[q] * isg;
                zq[q] = zv;
                float sgm = softplusf(gsv[q]);
                float dm  = m - sgm;
                klacc += logf(sgm / isg)
                       + (isg * isg + dm * dm) / (2.f * sgm * sgm) - 0.5f;
            }
            *(float4*)(embs + (bl[bb] * 11 + 3) * 128 + d0) =
                make_float4(zq[0], zq[1], zq[2], zq[3]);
            __nv_bfloat162 p0 = __floats2bfloat162_rn(zq[0], zq[1]);
            __nv_bfloat162 p1 = __floats2bfloat162_rn(zq[2], zq[3]);
            ((__nv_bfloat162*)(g_zb + (size_t)bg * DD + d0))[0] = p0;
            ((__nv_bfloat162*)(g_zb + (size_t)bg * DD + d0))[1] = p1;
#pragma unroll
            for (int o = 16; o; o >>= 1) klacc += __shfl_xor_sync(0xffffffffu, klacc, o);
            if (lane == 0) g_kl[bg] = klacc;
        }
    }
    __syncthreads();

    // ---- picked context logits (fp32): 160 (b,c) pairs over 8 warps ----
    for (int pp = w; pp < 16 * CC; pp += 8) {
        int b = pp / CC, c = pp - b * CC;
        int bg = b0 + b;
        int n  = ctx[bg * CC + c];
        float4 w4 = ((const float4*)(W_gen + (size_t)n * DD))[lane];
        float4 z4 = *(const float4*)(embs + (b * 11 + 3) * 128 + d0);
        float d = z4.x * w4.x + z4.y * w4.y + z4.z * w4.z + z4.w * w4.w;
#pragma unroll
        for (int o = 16; o; o >>= 1) d += __shfl_xor_sync(0xffffffffu, d, o);
        if (lane == 0) atomicAdd(&g_R[bg], d + b_gen[n]);
    }
}

// ======================== k_logits: two arch paths ========================
#define MT_PER_CTA 8

#if HAS_TCGEN05
__device__ __forceinline__ uint32_t elect_one_pred() {
    uint32_t pred;
    asm volatile(
        "{\n\t.reg .pred p;\n\t"
        "elect.sync _|p, 0xFFFFFFFF;\n\t"
        "selp.b32 %0, 1, 0, p;\n\t}"
        : "=r"(pred));
    return pred;
}
#define MBARRIER_INIT(mbar, cnt) \
    asm volatile("mbarrier.init.shared.b64 [%0], %1;" :: "r"((uint32_t)(mbar)), "r"((uint32_t)(cnt)) : "memory")
#define MBARRIER_WAIT_PARITY(mbar, par) do { \
    uint32_t _m = (uint32_t)(mbar); uint32_t _p = (uint32_t)(par); uint32_t _d; \
    asm volatile("{\n\t.reg .pred p;\n\t" \
        "mbarrier.try_wait.parity.acquire.cta.shared::cta.b64 p, [%1], %2;\n\t" \
        "selp.b32 %0, 1, 0, p;\n\t}" : "=r"(_d) : "r"(_m), "r"(_p) : "memory"); \
    if (!_d) { \
        asm volatile("{\n\t.reg .pred P1;\n\t" \
            "WL_%=:\n\t" \
            "mbarrier.try_wait.parity.acquire.cta.shared::cta.b64 P1, [%0], %1, 0x989680;\n\t" \
            "@P1 bra.uni WD_%=;\n\t" \
            "bra.uni WL_%=;\n\t" \
            "WD_%=:\n\t}" :: "r"(_m), "r"(_p) : "memory"); \
    } } while (0)
#define TCGEN05_ALLOC(smem_addr, nCols) \
    asm volatile("tcgen05.alloc.cta_group::1.sync.aligned.shared::cta.b32 [%0], %1;" \
        :: "r"((uint32_t)(smem_addr)), "r"((uint32_t)(nCols)) : "memory")
#define TCGEN05_DEALLOC(tmem, nCols) \
    asm volatile("tcgen05.dealloc.cta_group::1.sync.aligned.b32 %0, %1;" :: "r"(tmem), "r"((uint32_t)(nCols)))
#define TCGEN05_RELINQUISH() \
    asm volatile("tcgen05.relinquish_alloc_permit.cta_group::1.sync.aligned;")
#define TCGEN05_COMMIT(mbar) \
    asm volatile("tcgen05.commit.cta_group::1.mbarrier::arrive::one.shared::cluster.b64 [%0];" \
        :: "r"((uint32_t)(mbar)) : "memory")
#define TCGEN05_FENCE_BEFORE() asm volatile("tcgen05.fence::before_thread_sync;" ::: "memory")
#define TCGEN05_FENCE_AFTER()  asm volatile("tcgen05.fence::after_thread_sync;" ::: "memory")
#define TCGEN05_WAIT_LD()      asm volatile("tcgen05.wait::ld.sync.aligned;" ::: "memory")
#define FENCE_PROXY_ASYNC()    asm volatile("fence.proxy.async.shared::cta;" ::: "memory")
#define TCGEN05_LD_32X32B_X32(r, tmem_addr) \
    asm volatile( \
        "tcgen05.ld.sync.aligned.32x32b.x32.b32 " \
        "{%0, %1, %2, %3, %4, %5, %6, %7, " \
        " %8, %9, %10, %11, %12, %13, %14, %15, " \
        " %16, %17, %18, %19, %20, %21, %22, %23, " \
        " %24, %25, %26, %27, %28, %29, %30, %31}, [%32];" \
        : "=r"((r)[0]),  "=r"((r)[1]),  "=r"((r)[2]),  "=r"((r)[3]), \
          "=r"((r)[4]),  "=r"((r)[5]),  "=r"((r)[6]),  "=r"((r)[7]), \
          "=r"((r)[8]),  "=r"((r)[9]),  "=r"((r)[10]), "=r"((r)[11]), \
          "=r"((r)[12]), "=r"((r)[13]), "=r"((r)[14]), "=r"((r)[15]), \
          "=r"((r)[16]), "=r"((r)[17]), "=r"((r)[18]), "=r"((r)[19]), \
          "=r"((r)[20]), "=r"((r)[21]), "=r"((r)[22]), "=r"((r)[23]), \
          "=r"((r)[24]), "=r"((r)[25]), "=r"((r)[26]), "=r"((r)[27]), \
          "=r"((r)[28]), "=r"((r)[29]), "=r"((r)[30]), "=r"((r)[31]) \
        : "r"(tmem_addr))
static constexpr uint64_t SMEM_DESC_BASE_SW128 =
    (uint64_t(2) << 61) | (uint64_t(1) << 46) | (uint64_t(64) << 32) | (uint64_t(1) << 16);
#define MAKE_SMEM_DESC(addr) (SMEM_DESC_BASE_SW128 | ((uint64_t)((addr) >> 4) & 0x3FFF))
#define IDESC_LOG 0x08200490u

__device__ __forceinline__ void mma_f16_ss(uint32_t d_tmem, uint64_t a_desc,
                                           uint64_t b_desc, uint32_t idesc, bool accum) {
    uint32_t en = accum ? 1u : 0u;
    asm volatile(
        "{\n\t.reg .pred p;\n\t"
        "setp.ne.u32 p, %4, 0;\n\t"
        "tcgen05.mma.cta_group::1.kind::f16 [%0], %1, %2, %3, {%5,%5,%5,%5}, p;\n\t}"
        :: "r"(d_tmem), "l"(a_desc), "l"(b_desc), "r"(idesc), "r"(en), "r"(0u)
        : "memory");
}

#define SM_TPTR  0
#define SM_MBAR0 8
#define SM_MBAR1 16
#define SM_BG    32
#define SM_W     1024
#define SM_Z0    (1024 + 32768)
#define SM_Z1    (1024 + 65536)

__device__ __forceinline__ void logits_epilogue(int lt, int mt, uint32_t sb, uint32_t tmem,
                                                const float* bg_s, int w, int lane) {
    const int q = lt & 1;
    MBARRIER_WAIT_PARITY(sb + (q ? SM_MBAR1 : SM_MBAR0), (lt >> 1) & 1);
    TCGEN05_FENCE_AFTER();
    const uint32_t woff = ((uint32_t)(w & 3)) << 21;
    const int cb = (w < 4) ? 0 : 64;
    const uint32_t dt = tmem + (uint32_t)(q * 128 + cb) + woff;
    uint32_t r0[32], r1[32];
    TCGEN05_LD_32X32B_X32(r0, dt);
    TCGEN05_LD_32X32B_X32(r1, dt + 32);
    TCGEN05_WAIT_LD();
    TCGEN05_FENCE_BEFORE();
    float acc = 0.f;
#pragma unroll
    for (int c = 0; c < 32; c++) acc += __expf(__uint_as_float(r0[c]) + bg_s[cb + c]);
#pragma unroll
    for (int c = 0; c < 32; c++) acc += __expf(__uint_as_float(r1[c]) + bg_s[cb + 32 + c]);
    atomicAdd(&g_S[mt * 128 + (w & 3) * 32 + lane], acc);
}
#endif  // HAS_TCGEN05

// ---- fallback helpers (baseline sm_103: mma.sync + ldmatrix + cp.async) ----
__device__ __forceinline__ void mma16816(float c[4], const uint32_t a[4],
                                         uint32_t b0, uint32_t b1) {
    asm volatile(
        "mma.sync.aligned.m16n8k16.row.col.f32.bf16.bf16.f32 "
        "{%0,%1,%2,%3},{%4,%5,%6,%7},{%8,%9},{%0,%1,%2,%3};\n"
        : "+f"(c[0]), "+f"(c[1]), "+f"(c[2]), "+f"(c[3])
        : "r"(a[0]), "r"(a[1]), "r"(a[2]), "r"(a[3]), "r"(b0), "r"(b1));
}
__device__ __forceinline__ void ldmatrix_x4(uint32_t r[4], uint32_t addr) {
    asm volatile("ldmatrix.sync.aligned.m8n8.x4.shared.b16 {%0,%1,%2,%3}, [%4];"
        : "=r"(r[0]), "=r"(r[1]), "=r"(r[2]), "=r"(r[3]) : "r"(addr));
}
#define CP_ASYNC16(dst, src) \
    asm volatile("cp.async.cg.shared.global [%0], [%1], 16;" :: "r"(dst), "l"(src))
#define CP_COMMIT()  asm volatile("cp.async.commit_group;" ::: "memory")
#define CP_WAIT(n)   asm volatile("cp.async.wait_group %0;" :: "n"(n) : "memory")

#define TLD    136
#define FB_WS  69632
#define FB_BG  104448
#define SMEM_LOG 104960

__device__ __forceinline__ void fb_prefetch(uint32_t sb, int mt, int p, int tid) {
#pragma unroll
    for (int idx = tid; idx < 2048; idx += 256) {
        int r = idx >> 4, c = idx & 15;
        uint32_t dst = sb + (uint32_t)(p * 34816 + (r * TLD + c * 8) * 2);
        const void* src = (const void*)(g_zb + (size_t)(mt * 128 + r) * DD + c * 8);
        CP_ASYNC16(dst, src);
    }
    CP_COMMIT();
}

__global__ void __launch_bounds__(256, 2) k_logits(const float* __restrict__ W_gen,
                                                   const float* __restrict__ b_gen) {
#if HAS_TCGEN05
    extern __shared__ __align__(16) char smem[];
    const uint32_t sb = smem_to_u32(smem);
    const int tid  = threadIdx.x;
    const int w    = tid >> 5;
    const int lane = tid & 31;
    const int n0   = blockIdx.x * 128;
    const int mt0  = blockIdx.y * MT_PER_CTA;

    if (w == 0) { TCGEN05_ALLOC(sb + SM_TPTR, 256); TCGEN05_RELINQUISH(); }
    if (tid == 0) { MBARRIER_INIT(sb + SM_MBAR0, 1); MBARRIER_INIT(sb + SM_MBAR1, 1); }

    for (int gidx = tid; gidx < 2048; gidx += 256) {
        int r  = gidx >> 4;
        int g8 = gidx & 15;
        int n  = n0 + r;
        uint4 outv = make_uint4(0u, 0u, 0u, 0u);
        if (n < NV) {
            const float4* src = (const float4*)(W_gen + (size_t)n * DD + g8 * 8);
            float4 f0 = src[0], f1 = src[1];
            __nv_bfloat162 h0 = __floats2bfloat162_rn(f0.x, f0.y);
            __nv_bfloat162 h1 = __floats2bfloat162_rn(f0.z, f0.w);
            __nv_bfloat162 h2 = __floats2bfloat162_rn(f1.x, f1.y);
            __nv_bfloat162 h3 = __floats2bfloat162_rn(f1.z, f1.w);
            outv.x = *(uint32_t*)&h0; outv.y = *(uint32_t*)&h1;
            outv.z = *(uint32_t*)&h2; outv.w = *(uint32_t*)&h3;
        }
        int half = g8 >> 3;
        uint32_t boff = (uint32_t)(r * 128 + (g8 & 7) * 16);
        uint32_t sw = boff ^ ((boff >> 3) & 0x70);
        *(uint4*)(smem + SM_W + half * 16384 + sw) = outv;
    }
    if (tid < 128) {
        int n = n0 + tid;
        ((float*)(smem + SM_BG))[tid] = (n < NV) ? b_gen[n] : -88.0f;
    }
    FENCE_PROXY_ASYNC();
    __syncthreads();

    uint32_t tmem;
    asm volatile("ld.shared.b32 %0, [%1];" : "=r"(tmem) : "r"(sb + SM_TPTR));
    const float* bg_s = (const float*)(smem + SM_BG);

    const uint64_t bd0 = MAKE_SMEM_DESC(sb + SM_W);
    const uint64_t bd1 = MAKE_SMEM_DESC(sb + SM_W + 16384);

    for (int lt = 0; lt < MT_PER_CTA; lt++) {
        const int mt = mt0 + lt;
        const int p = lt & 1, k = lt >> 1;
        const uint32_t zoff = p ? SM_Z1 : SM_Z0;
        if (lt >= 2) MBARRIER_WAIT_PARITY(sb + (p ? SM_MBAR1 : SM_MBAR0), (k - 1) & 1);
        for (int gidx = tid; gidx < 2048; gidx += 256) {
            int r = gidx >> 4, g8 = gidx & 15;
            uint4 val = *(const uint4*)(g_zb + ((size_t)(mt * 128 + r)) * DD + g8 * 8);
            int half = g8 >> 3;
            uint32_t boff = (uint32_t)(r * 128 + (g8 & 7) * 16);
            uint32_t sw = boff ^ ((boff >> 3) & 0x70);
            *(uint4*)(smem + zoff + half * 16384 + sw) = val;
        }
        FENCE_PROXY_ASYNC();
        __syncthreads();
        if (w == 0) {
            TCGEN05_FENCE_AFTER();
            if (elect_one_pred()) {
                const uint64_t ad0 = MAKE_SMEM_DESC(sb + zoff);
                const uint64_t ad1 = MAKE_SMEM_DESC(sb + zoff + 16384);
                const uint32_t dt = tmem + (uint32_t)(p * 128);
#pragma unroll
                for (int s = 0; s < 8; s++) {
                    uint64_t ad = ((s >> 2) ? ad1 : ad0) + (uint64_t)((s & 3) * 2);
                    uint64_t bd = ((s >> 2) ? bd1 : bd0) + (uint64_t)((s & 3) * 2);
                    mma_f16_ss(dt, ad, bd, IDESC_LOG, s > 0);
                }
                TCGEN05_COMMIT(sb + (p ? SM_MBAR1 : SM_MBAR0));
            }
        }
        if (lt >= 1) logits_epilogue(lt - 1, mt - 1, sb, tmem, bg_s, w, lane);
    }
    logits_epilogue(MT_PER_CTA - 1, mt0 + MT_PER_CTA - 1, sb, tmem, bg_s, w, lane);
    __syncthreads();
    if (w == 0) TCGEN05_DEALLOC(tmem, 256);
#else
    extern __shared__ __align__(16) char smem[];
    const uint32_t sb = smem_to_u32(smem);
    __nv_bfloat16* Ws = (__nv_bfloat16*)(smem + FB_WS);
    float* bg_s = (float*)(smem + FB_BG);

    const int tid = threadIdx.x;
    const int n0  = blockIdx.x * 128;
    const int mt0 = blockIdx.y * MT_PER_CTA;

    for (int gidx = tid; gidx < 2048; gidx += 256) {
        int r = gidx >> 4, c = gidx & 15;
        int n = n0 + r;
        uint4 outv = make_uint4(0u, 0u, 0u, 0u);
        if (n < NV) {
            const float4* src = (const float4*)(W_gen + (size_t)n * DD + c * 8);
            float4 f0 = src[0], f1 = src[1];
            __nv_bfloat162 h0 = __floats2bfloat162_rn(f0.x, f0.y);
            __nv_bfloat162 h1 = __floats2bfloat162_rn(f0.z, f0.w);
            __nv_bfloat162 h2 = __floats2bfloat162_rn(f1.x, f1.y);
            __nv_bfloat162 h3 = __floats2bfloat162_rn(f1.z, f1.w);
            outv.x = *(uint32_t*)&h0; outv.y = *(uint32_t*)&h1;
            outv.z = *(uint32_t*)&h2; outv.w = *(uint32_t*)&h3;
        }
        *(uint4*)(Ws + r * TLD + c * 8) = outv;
    }
    if (tid < 128) {
        int n = n0 + tid;
        bg_s[tid] = (n < NV) ? b_gen[n] : -88.0f;
    }

    const int w    = tid >> 5;
    const int lane = tid & 31;
    const int g    = lane >> 2;
    const int t    = lane & 3;
    const int wm   = w & 3;
    const int wn   = w >> 2;

    const uint32_t aLane = (uint32_t)(((wm * 32 + (lane & 15)) * TLD + ((lane & 16) >> 1)) * 2);
    uint32_t bAddr[4];
#pragma unroll
    for (int jp = 0; jp < 4; jp++)
        bAddr[jp] = sb + FB_WS +
            (uint32_t)(((wn * 64 + jp * 16 + ((lane & 16) >> 1) + (lane & 7)) * TLD + (lane & 8)) * 2);

    fb_prefetch(sb, mt0, 0, tid);

    for (int lt = 0; lt < MT_PER_CTA; lt++) {
        const int p = lt & 1;
        if (lt + 1 < MT_PER_CTA) { fb_prefetch(sb, mt0 + lt + 1, p ^ 1, tid); CP_WAIT(1); }
        else                     { CP_WAIT(0); }
        __syncthreads();
        const uint32_t aBase0 = sb + (uint32_t)(p * 34816) + aLane;
        const uint32_t aBase1 = aBase0 + (uint32_t)(16 * TLD * 2);

        float acc[2][8][4];
#pragma unroll
        for (int i = 0; i < 2; i++)
#pragma unroll
            for (int j = 0; j < 8; j++)
#pragma unroll
                for (int q = 0; q < 4; q++) acc[i][j][q] = 0.f;

#pragma unroll
        for (int kk = 0; kk < 8; kk++) {
            const uint32_t kb = (uint32_t)(kk * 32);
            uint32_t a0[4], a1[4];
            ldmatrix_x4(a0, aBase0 + kb);
            ldmatrix_x4(a1, aBase1 + kb);
#pragma unroll
            for (int jp = 0; jp < 4; jp++) {
                uint32_t bq[4];
                ldmatrix_x4(bq, bAddr[jp] + kb);
                mma16816(acc[0][2 * jp],     a0, bq[0], bq[1]);
                mma16816(acc[1][2 * jp],     a1, bq[0], bq[1]);
                mma16816(acc[0][2 * jp + 1], a0, bq[2], bq[3]);
                mma16816(acc[1][2 * jp + 1], a1, bq[2], bq[3]);
            }
        }

        const int mt = mt0 + lt;
#pragma unroll
        for (int i = 0; i < 2; i++) {
            float rs0 = 0.f, rs1 = 0.f;
#pragma unroll
            for (int j = 0; j < 8; j++) {
                int nl = wn * 64 + j * 8 + 2 * t;
                float bg0 = bg_s[nl], bg1 = bg_s[nl + 1];
                rs0 += __expf(acc[i][j][0] + bg0) + __expf(acc[i][j][1] + bg1);
                rs1 += __expf(acc[i][j][2] + bg0) + __expf(acc[i][j][3] + bg1);
            }
            rs0 += __shfl_xor_sync(0xffffffffu, rs0, 1);
            rs0 += __shfl_xor_sync(0xffffffffu, rs0, 2);
            rs1 += __shfl_xor_sync(0xffffffffu, rs1, 1);
            rs1 += __shfl_xor_sync(0xffffffffu, rs1, 2);
            if (t == 0) {
                int m = mt * 128 + wm * 32 + i * 16 + g;
                atomicAdd(&g_S[m], rs0);
                atomicAdd(&g_S[m + 8], rs1);
            }
        }
        __syncthreads();
    }
#endif
}

// ---------------- kernel 3: final reduction ----------------
__global__ void __launch_bounds__(1024) k_final(float* __restrict__ out) {
    __shared__ float red[1024];
    const int tid = threadIdx.x;
    float a = 0.f;
    for (int i = tid; i < BB_; i += 1024)
        a += g_kl[i] - g_R[i] + (float)CC * __logf(g_S[i]);
    red[tid] = a;
    __syncthreads();
    for (int s = 512; s; s >>= 1) {
        if (tid < s) red[tid] += red[tid + s];
        __syncthreads();
    }
    if (tid == 0) out[0] = red[0] / (float)BB_;
}

// ---------------- launch ----------------
extern "C" void kernel_launch(void* const* d_in, const int* in_sizes, int n_in,
                              void* d_out, int out_size) {
    const int*   x_batch = (const int*)  d_in[0];
    const int*   ctx     = (const int*)  d_in[1];
    const float* eps     = (const float*)d_in[2];
    const float* inf_emb = (const float*)d_in[3];
    const float* W_aff   = (const float*)d_in[4];
    const float* b_aff   = (const float*)d_in[5];
    const float* W_mu    = (const float*)d_in[6];
    const float* b_mu    = (const float*)d_in[7];
    const float* W_sig   = (const float*)d_in[8];
    const float* b_sig   = (const float*)d_in[9];
    const float* gse     = (const float*)d_in[10];
    const float* W_gen   = (const float*)d_in[11];
    const float* b_gen   = (const float*)d_in[12];

    const int SMEM_A = (256 * WT_LD + 176 * 128) * 4;   // 229376 B
    cudaFuncSetAttribute(k_infnet, cudaFuncAttributeMaxDynamicSharedMemorySize, SMEM_A);
    cudaFuncSetAttribute(k_logits, cudaFuncAttributeMaxDynamicSharedMemorySize, SMEM_LOG);

    k_infnet<<<128, 256, SMEM_A>>>(x_batch, ctx, eps, inf_emb, W_aff, b_aff,
                                   W_mu, b_mu, W_sig, b_sig, gse, W_gen, b_gen);
    k_logits<<<dim3(NPAD / 128, 2), 256, SMEM_LOG>>>(W_gen, b_gen);
    k_final<<<1, 1024>>>((float*)d_out);
}

// round 8
// speedup vs baseline: 1.1475x; 1.0023x over previous
#include <cuda_runtime.h>
#include <cuda_bf16.h>
#include <math.h>
#include <stdint.h>

#define NV   50257
#define NPAD 50304          // 393 * 128
#define DD   128
#define BB_  2048
#define CC   10

// Does THIS compilation pass support tcgen05? (sm_103a / sm_100a arch-specific,
// or family-specific). Plain sm_103 pass compiles the mma.sync fallback.
#if defined(__CUDA_ARCH__) && (defined(__CUDA_ARCH_FEAT_SM103_ALL) || \
    defined(__CUDA_ARCH_FEAT_SM100_ALL) || defined(__CUDA_ARCH_FAMILY_SPECIFIC__))
#define HAS_TCGEN05 1
#else
#define HAS_TCGEN05 0
#endif

typedef unsigned long long u64;

// ---------------- scratch (static __device__ — allocation-free) ----------------
__device__ __align__(16) __nv_bfloat16 g_zb[BB_ * DD];    // z in bf16
__device__ float g_S[BB_];                                // sum exp(logits) per row
__device__ float g_R[BB_];                                // sum of picked logits per row
__device__ float g_kl[BB_];

// ---------------- common helpers ----------------
__device__ __forceinline__ uint32_t smem_to_u32(const void* p) {
    uint32_t a;
    asm("{ .reg .u64 t; cvta.to.shared.u64 t, %1; cvt.u32.u64 %0, t; }"
        : "=r"(a) : "l"(p));
    return a;
}
__device__ __forceinline__ float softplusf(float x) {
    return fmaxf(x, 0.f) + log1pf(expf(-fabsf(x)));
}
// ---- packed fp32x2 (Blackwell baseline sm_100+) ----
__device__ __forceinline__ void fma2(u64& d, u64 a, u64 b) {
    asm("fma.rn.f32x2 %0, %1, %2, %0;" : "+l"(d) : "l"(a), "l"(b));
}
__device__ __forceinline__ u64 pack2(float x) {
    u64 r; asm("mov.b64 %0, {%1, %1};" : "=l"(r) : "f"(x)); return r;
}
__device__ __forceinline__ u64 packxy(float x, float y) {
    u64 r; asm("mov.b64 %0, {%1, %2};" : "=l"(r) : "f"(x), "f"(y)); return r;
}
__device__ __forceinline__ void unpack2(float& lo, float& hi, u64 v) {
    asm("mov.b64 {%0, %1}, %2;" : "=f"(lo), "=f"(hi) : "l"(v));
}

// ---------------- kernel 1: inference network + KL + z + ctx-logits ----------------
// 128 CTAs x 512 threads (16 warps = 4/SMSP for latency hiding).
// Warp wq = w&7 owns batches {wq, wq+8}; half wh = w>>3 owns contexts
// [wh*5, wh*5+5) with FULL 128-e dots (no in-loop reduction).
#define WT_LD 136
__global__ void __launch_bounds__(512) k_infnet(
    const int* __restrict__ x_batch, const int* __restrict__ ctx,
    const float* __restrict__ eps, const float* __restrict__ inf_emb,
    const float* __restrict__ W_aff, const float* __restrict__ b_aff,
    const float* __restrict__ W_mu,  const float* __restrict__ b_mu,
    const float* __restrict__ W_sig, const float* __restrict__ b_sig,
    const float* __restrict__ gen_sigma_emb,
    const float* __restrict__ W_gen, const float* __restrict__ b_gen)
{
    extern __shared__ float sm[];
    float* Wt   = sm;                       // 256*136 floats
    float* embs = sm + 256 * WT_LD;         // 176*128 floats

    const int tid  = threadIdx.x;
    const int w    = tid >> 5;
    const int lane = tid & 31;
    const int wh   = w >> 3;                // context half
    const int wq   = w & 7;
    const int b0   = blockIdx.x * 16;

    if (tid < 16) { g_S[b0 + tid] = 0.f; g_R[b0 + tid] = 0.f; }

    // stage W_aff transposed: Wt[e][d] = W_aff[d][e]
    for (int idx = tid; idx < 128 * 256; idx += 512) {
        int d = idx >> 8, e = idx & 255;
        Wt[e * WT_LD + d] = W_aff[idx];
    }
    // stage embeddings: row r = b*11 + j ; j==0 -> center, else ctx[j-1]
    for (int r = w; r < 176; r += 16) {
        int b = r / 11, j = r - b * 11;
        int bg = b0 + b;
        int word = (j == 0) ? x_batch[bg] : ctx[bg * CC + (j - 1)];
        const float4* src = (const float4*)(inf_emb + (size_t)word * DD);
        ((float4*)(embs + r * 128))[lane] = src[lane];
    }
    __syncthreads();

    const int d0 = lane * 4;
    float4 ba = *(const float4*)(b_aff + d0);

    int bl[2] = {wq, wq + 8};

    // ---- s0 = b_aff + center . W_aff[:,0:128]  (full 128 e, both halves) ----
    u64 s2[2][2];
#pragma unroll
    for (int bb = 0; bb < 2; bb++) {
        s2[bb][0] = packxy(ba.x, ba.y);
        s2[bb][1] = packxy(ba.z, ba.w);
    }
    for (int e4 = 0; e4 < 128; e4 += 4) {
        float cv[2][4];
#pragma unroll
        for (int bb = 0; bb < 2; bb++)
            *(float4*)cv[bb] = *(const float4*)(embs + (bl[bb] * 11) * 128 + e4);
#pragma unroll
        for (int q = 0; q < 4; q++) {
            ulonglong2 wv = *(const ulonglong2*)(Wt + (e4 + q) * WT_LD + d0);
#pragma unroll
            for (int bb = 0; bb < 2; bb++) {
                u64 c2 = pack2(cv[bb][q]);
                fma2(s2[bb][0], c2, wv.x);
                fma2(s2[bb][1], c2, wv.y);
            }
        }
    }

    // ---- context loop: this half's 5 contexts, full e, no barriers ----
    float hsum[2][4];
#pragma unroll
    for (int bb = 0; bb < 2; bb++)
#pragma unroll
        for (int q = 0; q < 4; q++) hsum[bb][q] = 0.f;

    const int c0 = wh * 5;
    for (int c = 0; c < 5; c++) {
        u64 h2[2][2];
#pragma unroll
        for (int bb = 0; bb < 2; bb++) { h2[bb][0] = s2[bb][0]; h2[bb][1] = s2[bb][1]; }
        const int crow = 1 + c0 + c;
        for (int e4 = 0; e4 < 128; e4 += 4) {
            float cv[2][4];
#pragma unroll
            for (int bb = 0; bb < 2; bb++)
                *(float4*)cv[bb] = *(const float4*)(embs + (bl[bb] * 11 + crow) * 128 + e4);
#pragma unroll
            for (int q = 0; q < 4; q++) {
                ulonglong2 wv = *(const ulonglong2*)(Wt + (128 + e4 + q) * WT_LD + d0);
#pragma unroll
                for (int bb = 0; bb < 2; bb++) {
                    u64 c2 = pack2(cv[bb][q]);
                    fma2(h2[bb][0], c2, wv.x);
                    fma2(h2[bb][1], c2, wv.y);
                }
            }
        }
#pragma unroll
        for (int bb = 0; bb < 2; bb++) {
            float v0, v1, v2, v3;
            unpack2(v0, v1, h2[bb][0]);
            unpack2(v2, v3, h2[bb][1]);
            hsum[bb][0] += fmaxf(v0, 0.f);
            hsum[bb][1] += fmaxf(v1, 0.f);
            hsum[bb][2] += fmaxf(v2, 0.f);
            hsum[bb][3] += fmaxf(v3, 0.f);
        }
    }
    __syncthreads();   // all warps done reading Wt (W_aff) and embs ctx rows

    // dead-row reuse inside embs:
    //   trow(b) = row b*11   (center, dead)  : wh1 hsum transfer
    //   hrow(b) = row b*11+1 (ctx0, dead)    : combined hsum
    //   srow(b) = row b*11+2 (ctx1, dead)    : sigma pre-activation
    //   zrow(b) = row b*11+3 (ctx2, dead)    : z values
    if (wh == 1) {
#pragma unroll
        for (int bb = 0; bb < 2; bb++)
            *(float4*)(embs + (bl[bb] * 11) * 128 + d0) =
                make_float4(hsum[bb][0], hsum[bb][1], hsum[bb][2], hsum[bb][3]);
    }
    // stage W_mu^T (rows 0..127) and W_sig^T (rows 128..255) into Wt
    for (int idx = tid; idx < 128 * 128; idx += 512) {
        int d = idx >> 7, k = idx & 127;
        Wt[k * WT_LD + d]         = W_mu[idx];
        Wt[(128 + k) * WT_LD + d] = W_sig[idx];
    }
    __syncthreads();

    if (wh == 0) {
#pragma unroll
        for (int bb = 0; bb < 2; bb++) {
            float4 o4 = *(const float4*)(embs + (bl[bb] * 11) * 128 + d0);
            *(float4*)(embs + (bl[bb] * 11 + 1) * 128 + d0) =
                make_float4(hsum[bb][0] + o4.x, hsum[bb][1] + o4.y,
                            hsum[bb][2] + o4.z, hsum[bb][3] + o4.w);
        }
    }
    __syncthreads();

    // ---- GEMV: wh==0 -> mu, wh==1 -> sig, packed fp32x2 ----
    float4 bias4 = (wh == 0) ? *(const float4*)(b_mu + d0)
                             : *(const float4*)(b_sig + d0);
    u64 a2[2][2];
#pragma unroll
    for (int bb = 0; bb < 2; bb++) {
        a2[bb][0] = packxy(bias4.x, bias4.y);
        a2[bb][1] = packxy(bias4.z, bias4.w);
    }
    const int krow0 = wh * 128;
    for (int k4 = 0; k4 < 128; k4 += 4) {
        float hv[2][4];
#pragma unroll
        for (int bb = 0; bb < 2; bb++)
            *(float4*)hv[bb] = *(const float4*)(embs + (bl[bb] * 11 + 1) * 128 + k4);
#pragma unroll
        for (int q = 0; q < 4; q++) {
            ulonglong2 w2 = *(const ulonglong2*)(Wt + (krow0 + k4 + q) * WT_LD + d0);
#pragma unroll
            for (int bb = 0; bb < 2; bb++) {
                u64 h2p = pack2(hv[bb][q]);
                fma2(a2[bb][0], h2p, w2.x);
                fma2(a2[bb][1], h2p, w2.y);
            }
        }
    }
    float acc[2][4];
#pragma unroll
    for (int bb = 0; bb < 2; bb++) {
        unpack2(acc[bb][0], acc[bb][1], a2[bb][0]);
        unpack2(acc[bb][2], acc[bb][3], a2[bb][1]);
    }

    if (wh == 1) {
#pragma unroll
        for (int bb = 0; bb < 2; bb++)
            *(float4*)(embs + (bl[bb] * 11 + 2) * 128 + d0) =
                make_float4(acc[bb][0], acc[bb][1], acc[bb][2], acc[bb][3]);
    }
    __syncthreads();

    if (wh == 0) {
#pragma unroll
        for (int bb = 0; bb < 2; bb++) {
            int bg = b0 + bl[bb];
            int xb = x_batch[bg];
            float4 sg4 = *(const float4*)(embs + (bl[bb] * 11 + 2) * 128 + d0);
            float4 ep4 = *(const float4*)(eps + (size_t)bg * DD + d0);
            float4 gs4 = *(const float4*)(gen_sigma_emb + (size_t)xb * DD + d0);
            float sgv[4] = {sg4.x, sg4.y, sg4.z, sg4.w};
            float epv[4] = {ep4.x, ep4.y, ep4.z, ep4.w};
            float gsv[4] = {gs4.x, gs4.y, gs4.z, gs4.w};
            float zq[4];
            float klacc = 0.f;
#pragma unroll
            for (int q = 0; q < 4; q++) {
                float m   = acc[bb][q];
                float isg = softplusf(sgv[q]);
                float zv  = m + epv[q] * isg;
                zq[q] = zv;
                float sgm = softplusf(gsv[q]);
                float dm  = m - sgm;
                klacc += logf(sgm / isg)
                       + (isg * isg + dm * dm) / (2.f * sgm * sgm) - 0.5f;
            }
            *(float4*)(embs + (bl[bb] * 11 + 3) * 128 + d0) =
                make_float4(zq[0], zq[1], zq[2], zq[3]);
            __nv_bfloat162 p0 = __floats2bfloat162_rn(zq[0], zq[1]);
            __nv_bfloat162 p1 = __floats2bfloat162_rn(zq[2], zq[3]);
            ((__nv_bfloat162*)(g_zb + (size_t)bg * DD + d0))[0] = p0;
            ((__nv_bfloat162*)(g_zb + (size_t)bg * DD + d0))[1] = p1;
#pragma unroll
            for (int o = 16; o; o >>= 1) klacc += __shfl_xor_sync(0xffffffffu, klacc, o);
            if (lane == 0) g_kl[bg] = klacc;
        }
    }
    __syncthreads();

    // ---- picked context logits (fp32): 160 (b,c) pairs over 16 warps ----
    for (int pp = w; pp < 16 * CC; pp += 16) {
        int b = pp / CC, c = pp - b * CC;
        int bg = b0 + b;
        int n  = ctx[bg * CC + c];
        float4 w4 = ((const float4*)(W_gen + (size_t)n * DD))[lane];
        float4 z4 = *(const float4*)(embs + (b * 11 + 3) * 128 + d0);
        float d = z4.x * w4.x + z4.y * w4.y + z4.z * w4.z + z4.w * w4.w;
#pragma unroll
        for (int o = 16; o; o >>= 1) d += __shfl_xor_sync(0xffffffffu, d, o);
        if (lane == 0) atomicAdd(&g_R[bg], d + b_gen[n]);
    }
}

// ======================== k_logits: two arch paths ========================
#define MT_PER_CTA 8

#if HAS_TCGEN05
__device__ __forceinline__ uint32_t elect_one_pred() {
    uint32_t pred;
    asm volatile(
        "{\n\t.reg .pred p;\n\t"
        "elect.sync _|p, 0xFFFFFFFF;\n\t"
        "selp.b32 %0, 1, 0, p;\n\t}"
        : "=r"(pred));
    return pred;
}
#define MBARRIER_INIT(mbar, cnt) \
    asm volatile("mbarrier.init.shared.b64 [%0], %1;" :: "r"((uint32_t)(mbar)), "r"((uint32_t)(cnt)) : "memory")
#define MBARRIER_WAIT_PARITY(mbar, par) do { \
    uint32_t _m = (uint32_t)(mbar); uint32_t _p = (uint32_t)(par); uint32_t _d; \
    asm volatile("{\n\t.reg .pred p;\n\t" \
        "mbarrier.try_wait.parity.acquire.cta.shared::cta.b64 p, [%1], %2;\n\t" \
        "selp.b32 %0, 1, 0, p;\n\t}" : "=r"(_d) : "r"(_m), "r"(_p) : "memory"); \
    if (!_d) { \
        asm volatile("{\n\t.reg .pred P1;\n\t" \
            "WL_%=:\n\t" \
            "mbarrier.try_wait.parity.acquire.cta.shared::cta.b64 P1, [%0], %1, 0x989680;\n\t" \
            "@P1 bra.uni WD_%=;\n\t" \
            "bra.uni WL_%=;\n\t" \
            "WD_%=:\n\t}" :: "r"(_m), "r"(_p) : "memory"); \
    } } while (0)
#define TCGEN05_ALLOC(smem_addr, nCols) \
    asm volatile("tcgen05.alloc.cta_group::1.sync.aligned.shared::cta.b32 [%0], %1;" \
        :: "r"((uint32_t)(smem_addr)), "r"((uint32_t)(nCols)) : "memory")
#define TCGEN05_DEALLOC(tmem, nCols) \
    asm volatile("tcgen05.dealloc.cta_group::1.sync.aligned.b32 %0, %1;" :: "r"(tmem), "r"((uint32_t)(nCols)))
#define TCGEN05_RELINQUISH() \
    asm volatile("tcgen05.relinquish_alloc_permit.cta_group::1.sync.aligned;")
#define TCGEN05_COMMIT(mbar) \
    asm volatile("tcgen05.commit.cta_group::1.mbarrier::arrive::one.shared::cluster.b64 [%0];" \
        :: "r"((uint32_t)(mbar)) : "memory")
#define TCGEN05_FENCE_BEFORE() asm volatile("tcgen05.fence::before_thread_sync;" ::: "memory")
#define TCGEN05_FENCE_AFTER()  asm volatile("tcgen05.fence::after_thread_sync;" ::: "memory")
#define TCGEN05_WAIT_LD()      asm volatile("tcgen05.wait::ld.sync.aligned;" ::: "memory")
#define FENCE_PROXY_ASYNC()    asm volatile("fence.proxy.async.shared::cta;" ::: "memory")
#define TCGEN05_LD_32X32B_X32(r, tmem_addr) \
    asm volatile( \
        "tcgen05.ld.sync.aligned.32x32b.x32.b32 " \
        "{%0, %1, %2, %3, %4, %5, %6, %7, " \
        " %8, %9, %10, %11, %12, %13, %14, %15, " \
        " %16, %17, %18, %19, %20, %21, %22, %23, " \
        " %24, %25, %26, %27, %28, %29, %30, %31}, [%32];" \
        : "=r"((r)[0]),  "=r"((r)[1]),  "=r"((r)[2]),  "=r"((r)[3]), \
          "=r"((r)[4]),  "=r"((r)[5]),  "=r"((r)[6]),  "=r"((r)[7]), \
          "=r"((r)[8]),  "=r"((r)[9]),  "=r"((r)[10]), "=r"((r)[11]), \
          "=r"((r)[12]), "=r"((r)[13]), "=r"((r)[14]), "=r"((r)[15]), \
          "=r"((r)[16]), "=r"((r)[17]), "=r"((r)[18]), "=r"((r)[19]), \
          "=r"((r)[20]), "=r"((r)[21]), "=r"((r)[22]), "=r"((r)[23]), \
          "=r"((r)[24]), "=r"((r)[25]), "=r"((r)[26]), "=r"((r)[27]), \
          "=r"((r)[28]), "=r"((r)[29]), "=r"((r)[30]), "=r"((r)[31]) \
        : "r"(tmem_addr))
static constexpr uint64_t SMEM_DESC_BASE_SW128 =
    (uint64_t(2) << 61) | (uint64_t(1) << 46) | (uint64_t(64) << 32) | (uint64_t(1) << 16);
#define MAKE_SMEM_DESC(addr) (SMEM_DESC_BASE_SW128 | ((uint64_t)((addr) >> 4) & 0x3FFF))
#define IDESC_LOG 0x08200490u

__device__ __forceinline__ void mma_f16_ss(uint32_t d_tmem, uint64_t a_desc,
                                           uint64_t b_desc, uint32_t idesc, bool accum) {
    uint32_t en = accum ? 1u : 0u;
    asm volatile(
        "{\n\t.reg .pred p;\n\t"
        "setp.ne.u32 p, %4, 0;\n\t"
        "tcgen05.mma.cta_group::1.kind::f16 [%0], %1, %2, %3, {%5,%5,%5,%5}, p;\n\t}"
        :: "r"(d_tmem), "l"(a_desc), "l"(b_desc), "r"(idesc), "r"(en), "r"(0u)
        : "memory");
}

#define SM_TPTR  0
#define SM_MBAR0 8
#define SM_MBAR1 16
#define SM_BG    32
#define SM_W     1024
#define SM_Z0    (1024 + 32768)
#define SM_Z1    (1024 + 65536)

__device__ __forceinline__ void logits_epilogue(int lt, int mt, uint32_t sb, uint32_t tmem,
                                                const float* bg_s, int w, int lane) {
    const int q = lt & 1;
    MBARRIER_WAIT_PARITY(sb + (q ? SM_MBAR1 : SM_MBAR0), (lt >> 1) & 1);
    TCGEN05_FENCE_AFTER();
    const uint32_t woff = ((uint32_t)(w & 3)) << 21;
    const int cb = (w < 4) ? 0 : 64;
    const uint32_t dt = tmem + (uint32_t)(q * 128 + cb) + woff;
    uint32_t r0[32], r1[32];
    TCGEN05_LD_32X32B_X32(r0, dt);
    TCGEN05_LD_32X32B_X32(r1, dt + 32);
    TCGEN05_WAIT_LD();
    TCGEN05_FENCE_BEFORE();
    float acc = 0.f;
#pragma unroll
    for (int c = 0; c < 32; c++) acc += __expf(__uint_as_float(r0[c]) + bg_s[cb + c]);
#pragma unroll
    for (int c = 0; c < 32; c++) acc += __expf(__uint_as_float(r1[c]) + bg_s[cb + 32 + c]);
    atomicAdd(&g_S[mt * 128 + (w & 3) * 32 + lane], acc);
}
#endif  // HAS_TCGEN05

// ---- fallback helpers (baseline sm_103: mma.sync + ldmatrix + cp.async) ----
__device__ __forceinline__ void mma16816(float c[4], const uint32_t a[4],
                                         uint32_t b0, uint32_t b1) {
    asm volatile(
        "mma.sync.aligned.m16n8k16.row.col.f32.bf16.bf16.f32 "
        "{%0,%1,%2,%3},{%4,%5,%6,%7},{%8,%9},{%0,%1,%2,%3};\n"
        : "+f"(c[0]), "+f"(c[1]), "+f"(c[2]), "+f"(c[3])
        : "r"(a[0]), "r"(a[1]), "r"(a[2]), "r"(a[3]), "r"(b0), "r"(b1));
}
__device__ __forceinline__ void ldmatrix_x4(uint32_t r[4], uint32_t addr) {
    asm volatile("ldmatrix.sync.aligned.m8n8.x4.shared.b16 {%0,%1,%2,%3}, [%4];"
        : "=r"(r[0]), "=r"(r[1]), "=r"(r[2]), "=r"(r[3]) : "r"(addr));
}
#define CP_ASYNC16(dst, src) \
    asm volatile("cp.async.cg.shared.global [%0], [%1], 16;" :: "r"(dst), "l"(src))
#define CP_COMMIT()  asm volatile("cp.async.commit_group;" ::: "memory")
#define CP_WAIT(n)   asm volatile("cp.async.wait_group %0;" :: "n"(n) : "memory")

#define TLD    136
#define FB_WS  69632
#define FB_BG  104448
#define SMEM_LOG 104960

__device__ __forceinline__ void fb_prefetch(uint32_t sb, int mt, int p, int tid) {
#pragma unroll
    for (int idx = tid; idx < 2048; idx += 256) {
        int r = idx >> 4, c = idx & 15;
        uint32_t dst = sb + (uint32_t)(p * 34816 + (r * TLD + c * 8) * 2);
        const void* src = (const void*)(g_zb + (size_t)(mt * 128 + r) * DD + c * 8);
        CP_ASYNC16(dst, src);
    }
    CP_COMMIT();
}

__global__ void __launch_bounds__(256, 2) k_logits(const float* __restrict__ W_gen,
                                                   const float* __restrict__ b_gen) {
#if HAS_TCGEN05
    extern __shared__ __align__(16) char smem[];
    const uint32_t sb = smem_to_u32(smem);
    const int tid  = threadIdx.x;
    const int w    = tid >> 5;
    const int lane = tid & 31;
    const int n0   = blockIdx.x * 128;
    const int mt0  = blockIdx.y * MT_PER_CTA;

    if (w == 0) { TCGEN05_ALLOC(sb + SM_TPTR, 256); TCGEN05_RELINQUISH(); }
    if (tid == 0) { MBARRIER_INIT(sb + SM_MBAR0, 1); MBARRIER_INIT(sb + SM_MBAR1, 1); }

    for (int gidx = tid; gidx < 2048; gidx += 256) {
        int r  = gidx >> 4;
        int g8 = gidx & 15;
        int n  = n0 + r;
        uint4 outv = make_uint4(0u, 0u, 0u, 0u);
        if (n < NV) {
            const float4* src = (const float4*)(W_gen + (size_t)n * DD + g8 * 8);
            float4 f0 = src[0], f1 = src[1];
            __nv_bfloat162 h0 = __floats2bfloat162_rn(f0.x, f0.y);
            __nv_bfloat162 h1 = __floats2bfloat162_rn(f0.z, f0.w);
            __nv_bfloat162 h2 = __floats2bfloat162_rn(f1.x, f1.y);
            __nv_bfloat162 h3 = __floats2bfloat162_rn(f1.z, f1.w);
            outv.x = *(uint32_t*)&h0; outv.y = *(uint32_t*)&h1;
            outv.z = *(uint32_t*)&h2; outv.w = *(uint32_t*)&h3;
        }
        int half = g8 >> 3;
        uint32_t boff = (uint32_t)(r * 128 + (g8 & 7) * 16);
        uint32_t sw = boff ^ ((boff >> 3) & 0x70);
        *(uint4*)(smem + SM_W + half * 16384 + sw) = outv;
    }
    if (tid < 128) {
        int n = n0 + tid;
        ((float*)(smem + SM_BG))[tid] = (n < NV) ? b_gen[n] : -88.0f;
    }
    FENCE_PROXY_ASYNC();
    __syncthreads();

    uint32_t tmem;
    asm volatile("ld.shared.b32 %0, [%1];" : "=r"(tmem) : "r"(sb + SM_TPTR));
    const float* bg_s = (const float*)(smem + SM_BG);

    const uint64_t bd0 = MAKE_SMEM_DESC(sb + SM_W);
    const uint64_t bd1 = MAKE_SMEM_DESC(sb + SM_W + 16384);

    for (int lt = 0; lt < MT_PER_CTA; lt++) {
        const int mt = mt0 + lt;
        const int p = lt & 1, k = lt >> 1;
        const uint32_t zoff = p ? SM_Z1 : SM_Z0;
        if (lt >= 2) MBARRIER_WAIT_PARITY(sb + (p ? SM_MBAR1 : SM_MBAR0), (k - 1) & 1);
        for (int gidx = tid; gidx < 2048; gidx += 256) {
            int r = gidx >> 4, g8 = gidx & 15;
            uint4 val = *(const uint4*)(g_zb + ((size_t)(mt * 128 + r)) * DD + g8 * 8);
            int half = g8 >> 3;
            uint32_t boff = (uint32_t)(r * 128 + (g8 & 7) * 16);
            uint32_t sw = boff ^ ((boff >> 3) & 0x70);
            *(uint4*)(smem + zoff + half * 16384 + sw) = val;
        }
        FENCE_PROXY_ASYNC();
        __syncthreads();
        if (w == 0) {
            TCGEN05_FENCE_AFTER();
            if (elect_one_pred()) {
                const uint64_t ad0 = MAKE_SMEM_DESC(sb + zoff);
                const uint64_t ad1 = MAKE_SMEM_DESC(sb + zoff + 16384);
                const uint32_t dt = tmem + (uint32_t)(p * 128);
#pragma unroll
                for (int s = 0; s < 8; s++) {
                    uint64_t ad = ((s >> 2) ? ad1 : ad0) + (uint64_t)((s & 3) * 2);
                    uint64_t bd = ((s >> 2) ? bd1 : bd0) + (uint64_t)((s & 3) * 2);
                    mma_f16_ss(dt, ad, bd, IDESC_LOG, s > 0);
                }
                TCGEN05_COMMIT(sb + (p ? SM_MBAR1 : SM_MBAR0));
            }
        }
        if (lt >= 1) logits_epilogue(lt - 1, mt - 1, sb, tmem, bg_s, w, lane);
    }
    logits_epilogue(MT_PER_CTA - 1, mt0 + MT_PER_CTA - 1, sb, tmem, bg_s, w, lane);
    __syncthreads();
    if (w == 0) TCGEN05_DEALLOC(tmem, 256);
#else
    extern __shared__ __align__(16) char smem[];
    const uint32_t sb = smem_to_u32(smem);
    __nv_bfloat16* Ws = (__nv_bfloat16*)(smem + FB_WS);
    float* bg_s = (float*)(smem + FB_BG);

    const int tid = threadIdx.x;
    const int n0  = blockIdx.x * 128;
    const int mt0 = blockIdx.y * MT_PER_CTA;

    for (int gidx = tid; gidx < 2048; gidx += 256) {
        int r = gidx >> 4, c = gidx & 15;
        int n = n0 + r;
        uint4 outv = make_uint4(0u, 0u, 0u, 0u);
        if (n < NV) {
            const float4* src = (const float4*)(W_gen + (size_t)n * DD + c * 8);
            float4 f0 = src[0], f1 = src[1];
            __nv_bfloat162 h0 = __floats2bfloat162_rn(f0.x, f0.y);
            __nv_bfloat162 h1 = __floats2bfloat162_rn(f0.z, f0.w);
            __nv_bfloat162 h2 = __floats2bfloat162_rn(f1.x, f1.y);
            __nv_bfloat162 h3 = __floats2bfloat162_rn(f1.z, f1.w);
            outv.x = *(uint32_t*)&h0; outv.y = *(uint32_t*)&h1;
            outv.z = *(uint32_t*)&h2; outv.w = *(uint32_t*)&h3;
        }
        *(uint4*)(Ws + r * TLD + c * 8) = outv;
    }
    if (tid < 128) {
        int n = n0 + tid;
        bg_s[tid] = (n < NV) ? b_gen[n] : -88.0f;
    }

    const int w    = tid >> 5;
    const int lane = tid & 31;
    const int g    = lane >> 2;
    const int t    = lane & 3;
    const int wm   = w & 3;
    const int wn   = w >> 2;

    const uint32_t aLane = (uint32_t)(((wm * 32 + (lane & 15)) * TLD + ((lane & 16) >> 1)) * 2);
    uint32_t bAddr[4];
#pragma unroll
    for (int jp = 0; jp < 4; jp++)
        bAddr[jp] = sb + FB_WS +
            (uint32_t)(((wn * 64 + jp * 16 + ((lane & 16) >> 1) + (lane & 7)) * TLD + (lane & 8)) * 2);

    fb_prefetch(sb, mt0, 0, tid);

    for (int lt = 0; lt < MT_PER_CTA; lt++) {
        const int p = lt & 1;
        if (lt + 1 < MT_PER_CTA) { fb_prefetch(sb, mt0 + lt + 1, p ^ 1, tid); CP_WAIT(1); }
        else                     { CP_WAIT(0); }
        __syncthreads();
        const uint32_t aBase0 = sb + (uint32_t)(p * 34816) + aLane;
        const uint32_t aBase1 = aBase0 + (uint32_t)(16 * TLD * 2);

        float acc[2][8][4];
#pragma unroll
        for (int i = 0; i < 2; i++)
#pragma unroll
            for (int j = 0; j < 8; j++)
#pragma unroll
                for (int q = 0; q < 4; q++) acc[i][j][q] = 0.f;

#pragma unroll
        for (int kk = 0; kk < 8; kk++) {
            const uint32_t kb = (uint32_t)(kk * 32);
            uint32_t a0[4], a1[4];
            ldmatrix_x4(a0, aBase0 + kb);
            ldmatrix_x4(a1, aBase1 + kb);
#pragma unroll
            for (int jp = 0; jp < 4; jp++) {
                uint32_t bq[4];
                ldmatrix_x4(bq, bAddr[jp] + kb);
                mma16816(acc[0][2 * jp],     a0, bq[0], bq[1]);
                mma16816(acc[1][2 * jp],     a1, bq[0], bq[1]);
                mma16816(acc[0][2 * jp + 1], a0, bq[2], bq[3]);
                mma16816(acc[1][2 * jp + 1], a1, bq[2], bq[3]);
            }
        }

        const int mt = mt0 + lt;
#pragma unroll
        for (int i = 0; i < 2; i++) {
            float rs0 = 0.f, rs1 = 0.f;
#pragma unroll
            for (int j = 0; j < 8; j++) {
                int nl = wn * 64 + j * 8 + 2 * t;
                float bg0 = bg_s[nl], bg1 = bg_s[nl + 1];
                rs0 += __expf(acc[i][j][0] + bg0) + __expf(acc[i][j][1] + bg1);
                rs1 += __expf(acc[i][j][2] + bg0) + __expf(acc[i][j][3] + bg1);
            }
            rs0 += __shfl_xor_sync(0xffffffffu, rs0, 1);
            rs0 += __shfl_xor_sync(0xffffffffu, rs0, 2);
            rs1 += __shfl_xor_sync(0xffffffffu, rs1, 1);
            rs1 += __shfl_xor_sync(0xffffffffu, rs1, 2);
            if (t == 0) {
                int m = mt * 128 + wm * 32 + i * 16 + g;
                atomicAdd(&g_S[m], rs0);
                atomicAdd(&g_S[m + 8], rs1);
            }
        }
        __syncthreads();
    }
#endif
}

// ---------------- kernel 3: final reduction ----------------
__global__ void __launch_bounds__(1024) k_final(float* __restrict__ out) {
    __shared__ float red[1024];
    const int tid = threadIdx.x;
    float a = 0.f;
    for (int i = tid; i < BB_; i += 1024)
        a += g_kl[i] - g_R[i] + (float)CC * __logf(g_S[i]);
    red[tid] = a;
    __syncthreads();
    for (int s = 512; s; s >>= 1) {
        if (tid < s) red[tid] += red[tid + s];
        __syncthreads();
    }
    if (tid == 0) out[0] = red[0] / (float)BB_;
}

// ---------------- launch ----------------
extern "C" void kernel_launch(void* const* d_in, const int* in_sizes, int n_in,
                              void* d_out, int out_size) {
    const int*   x_batch = (const int*)  d_in[0];
    const int*   ctx     = (const int*)  d_in[1];
    const float* eps     = (const float*)d_in[2];
    const float* inf_emb = (const float*)d_in[3];
    const float* W_aff   = (const float*)d_in[4];
    const float* b_aff   = (const float*)d_in[5];
    const float* W_mu    = (const float*)d_in[6];
    const float* b_mu    = (const float*)d_in[7];
    const float* W_sig   = (const float*)d_in[8];
    const float* b_sig   = (const float*)d_in[9];
    const float* gse     = (const float*)d_in[10];
    const float* W_gen   = (const float*)d_in[11];
    const float* b_gen   = (const float*)d_in[12];

    const int SMEM_A = (256 * WT_LD + 176 * 128) * 4;   // 229376 B
    cudaFuncSetAttribute(k_infnet, cudaFuncAttributeMaxDynamicSharedMemorySize, SMEM_A);
    cudaFuncSetAttribute(k_logits, cudaFuncAttributeMaxDynamicSharedMemorySize, SMEM_LOG);

    k_infnet<<<128, 512, SMEM_A>>>(x_batch, ctx, eps, inf_emb, W_aff, b_aff,
                                   W_mu, b_mu, W_sig, b_sig, gse, W_gen, b_gen);
    k_logits<<<dim3(NPAD / 128, 2), 256, SMEM_LOG>>>(W_gen, b_gen);
    k_final<<<1, 1024>>>((float*)d_out);
}

// round 9
// speedup vs baseline: 1.2106x; 1.0549x over previous
#include <cuda_runtime.h>
#include <cuda_bf16.h>
#include <math.h>
#include <stdint.h>

#define NV   50257
#define NPAD 50304          // 393 * 128
#define DD   128
#define BB_  2048
#define CC   10

// Does THIS compilation pass support tcgen05? (sm_103a / sm_100a arch-specific,
// or family-specific). Plain sm_103 pass compiles the mma.sync fallback.
#if defined(__CUDA_ARCH__) && (defined(__CUDA_ARCH_FEAT_SM103_ALL) || \
    defined(__CUDA_ARCH_FEAT_SM100_ALL) || defined(__CUDA_ARCH_FAMILY_SPECIFIC__))
#define HAS_TCGEN05 1
#else
#define HAS_TCGEN05 0
#endif

typedef unsigned long long u64;

// ---------------- scratch (static __device__ — allocation-free) ----------------
__device__ __align__(16) __nv_bfloat16 g_zb[BB_ * DD];    // z in bf16
__device__ float g_S[BB_];                                // sum exp(logits) per row
__device__ float g_R[BB_];                                // sum of picked logits per row
__device__ float g_kl[BB_];

// ---------------- common helpers ----------------
__device__ __forceinline__ uint32_t smem_to_u32(const void* p) {
    uint32_t a;
    asm("{ .reg .u64 t; cvta.to.shared.u64 t, %1; cvt.u32.u64 %0, t; }"
        : "=r"(a) : "l"(p));
    return a;
}
__device__ __forceinline__ float softplusf(float x) {
    return fmaxf(x, 0.f) + log1pf(expf(-fabsf(x)));
}
// ---- packed fp32x2 (Blackwell baseline sm_100+) ----
__device__ __forceinline__ void fma2(u64& d, u64 a, u64 b) {
    asm("fma.rn.f32x2 %0, %1, %2, %0;" : "+l"(d) : "l"(a), "l"(b));
}
__device__ __forceinline__ u64 pack2(float x) {
    u64 r; asm("mov.b64 %0, {%1, %1};" : "=l"(r) : "f"(x)); return r;
}
__device__ __forceinline__ u64 packxy(float x, float y) {
    u64 r; asm("mov.b64 %0, {%1, %2};" : "=l"(r) : "f"(x), "f"(y)); return r;
}
__device__ __forceinline__ void unpack2(float& lo, float& hi, u64 v) {
    asm("mov.b64 {%0, %1}, %2;" : "=f"(lo), "=f"(hi) : "l"(v));
}

// ---------------- kernel 1: inference network + KL + z + ctx-logits ----------------
// 128 CTAs x 512 threads (16 warps). Warp decomposition (crossbar-optimal):
//   dh = w&1      : d-half, d in [dh*64, dh*64+64); lane owns 2 d's (one u64 acc)
//   wq = (w>>1)&3 : batch quad, batches {wq*4..wq*4+3}
//   wh = w>>3     : context half (5 contexts each); also mu/sig split in GEMV
// Per e: Wt = 2 wf, cv = 1 wf (vs 4.5 before). s0 split over e-halves between
// wh warps and exchanged via dead smem rows (no duplicate center dot).
#define WT_LD 136
__global__ void __launch_bounds__(512) k_infnet(
    const int* __restrict__ x_batch, const int* __restrict__ ctx,
    const float* __restrict__ eps, const float* __restrict__ inf_emb,
    const float* __restrict__ W_aff, const float* __restrict__ b_aff,
    const float* __restrict__ W_mu,  const float* __restrict__ b_mu,
    const float* __restrict__ W_sig, const float* __restrict__ b_sig,
    const float* __restrict__ gen_sigma_emb,
    const float* __restrict__ W_gen, const float* __restrict__ b_gen)
{
    extern __shared__ float sm[];
    float* Wt   = sm;                       // 256*136 floats
    float* embs = sm + 256 * WT_LD;         // 176*128 floats

    const int tid  = threadIdx.x;
    const int w    = tid >> 5;
    const int lane = tid & 31;
    const int dh   = w & 1;
    const int wq   = (w >> 1) & 3;
    const int wh   = w >> 3;
    const int b0   = blockIdx.x * 16;
    const int d0   = dh * 64 + lane * 2;    // this lane's d-pair

    if (tid < 16) { g_S[b0 + tid] = 0.f; g_R[b0 + tid] = 0.f; g_kl[b0 + tid] = 0.f; }

    // stage W_aff transposed: Wt[e][d] = W_aff[d][e]
    for (int idx = tid; idx < 128 * 256; idx += 512) {
        int d = idx >> 8, e = idx & 255;
        Wt[e * WT_LD + d] = W_aff[idx];
    }
    // stage embeddings: row r = b*11 + j ; j==0 -> center, else ctx[j-1]
    for (int r = w; r < 176; r += 16) {
        int b = r / 11, j = r - b * 11;
        int bg = b0 + b;
        int word = (j == 0) ? x_batch[bg] : ctx[bg * CC + (j - 1)];
        const float4* src = (const float4*)(inf_emb + (size_t)word * DD);
        ((float4*)(embs + r * 128))[lane] = src[lane];
    }
    __syncthreads();

    int bl[4];
#pragma unroll
    for (int bb = 0; bb < 4; bb++) bl[bb] = wq * 4 + bb;

    // ---- s0 partial: e in [wh*64, wh*64+64) of center . W_aff[:,0:128] ----
    u64 s2[4] = {0ull, 0ull, 0ull, 0ull};
    const int es0 = wh * 64;
    for (int e4 = es0; e4 < es0 + 64; e4 += 4) {
        float cv[4][4];
#pragma unroll
        for (int bb = 0; bb < 4; bb++)
            *(float4*)cv[bb] = *(const float4*)(embs + (bl[bb] * 11) * 128 + e4);
#pragma unroll
        for (int q = 0; q < 4; q++) {
            u64 wv = *(const u64*)(Wt + (e4 + q) * WT_LD + d0);
#pragma unroll
            for (int bb = 0; bb < 4; bb++)
                fma2(s2[bb], pack2(cv[bb][q]), wv);
        }
    }
    // exchange halves through the (now dead) center rows; combine + b_aff
    if (wh == 1) {
#pragma unroll
        for (int bb = 0; bb < 4; bb++) {
            float lo, hi; unpack2(lo, hi, s2[bb]);
            *(float2*)(embs + (bl[bb] * 11) * 128 + d0) = make_float2(lo, hi);
        }
    }
    __syncthreads();
    if (wh == 0) {
        float2 bav = *(const float2*)(b_aff + d0);
#pragma unroll
        for (int bb = 0; bb < 4; bb++) {
            float2 o = *(const float2*)(embs + (bl[bb] * 11) * 128 + d0);
            float lo, hi; unpack2(lo, hi, s2[bb]);
            *(float2*)(embs + (bl[bb] * 11) * 128 + d0) =
                make_float2(lo + o.x + bav.x, hi + o.y + bav.y);
        }
    }
    __syncthreads();

    // ---- context loop: this half's 5 contexts, full 128 e, no barriers ----
    float hsum[4][2];
#pragma unroll
    for (int bb = 0; bb < 4; bb++) { hsum[bb][0] = 0.f; hsum[bb][1] = 0.f; }

    for (int c = 0; c < 5; c++) {
        const int crow = 1 + wh * 5 + c;
        u64 h2[4];
#pragma unroll
        for (int bb = 0; bb < 4; bb++) {
            float2 s = *(const float2*)(embs + (bl[bb] * 11) * 128 + d0);
            h2[bb] = packxy(s.x, s.y);
        }
        for (int e4 = 0; e4 < 128; e4 += 4) {
            float cv[4][4];
#pragma unroll
            for (int bb = 0; bb < 4; bb++)
                *(float4*)cv[bb] = *(const float4*)(embs + (bl[bb] * 11 + crow) * 128 + e4);
#pragma unroll
            for (int q = 0; q < 4; q++) {
                u64 wv = *(const u64*)(Wt + (128 + e4 + q) * WT_LD + d0);
#pragma unroll
                for (int bb = 0; bb < 4; bb++)
                    fma2(h2[bb], pack2(cv[bb][q]), wv);
            }
        }
#pragma unroll
        for (int bb = 0; bb < 4; bb++) {
            float lo, hi; unpack2(lo, hi, h2[bb]);
            hsum[bb][0] += fmaxf(lo, 0.f);
            hsum[bb][1] += fmaxf(hi, 0.f);
        }
    }
    __syncthreads();   // Wt (W_aff) and trow(s0) now dead

    // dead-row reuse: trow=b*11 (hsum transfer), hrow=b*11+1 (combined hsum),
    //                 srow=b*11+2 (sigma pre-act), zrow=b*11+3 (z)
    if (wh == 1) {
#pragma unroll
        for (int bb = 0; bb < 4; bb++)
            *(float2*)(embs + (bl[bb] * 11) * 128 + d0) =
                make_float2(hsum[bb][0], hsum[bb][1]);
    }
    // stage W_mu^T (rows 0..127) and W_sig^T (rows 128..255) into Wt
    for (int idx = tid; idx < 128 * 128; idx += 512) {
        int d = idx >> 7, k = idx & 127;
        Wt[k * WT_LD + d]         = W_mu[idx];
        Wt[(128 + k) * WT_LD + d] = W_sig[idx];
    }
    __syncthreads();

    if (wh == 0) {
#pragma unroll
        for (int bb = 0; bb < 4; bb++) {
            float2 o = *(const float2*)(embs + (bl[bb] * 11) * 128 + d0);
            *(float2*)(embs + (bl[bb] * 11 + 1) * 128 + d0) =
                make_float2(hsum[bb][0] + o.x, hsum[bb][1] + o.y);
        }
    }
    __syncthreads();

    // ---- GEMV: wh==0 -> mu, wh==1 -> sig (64-d half per warp) ----
    float2 bias = (wh == 0) ? *(const float2*)(b_mu + d0)
                            : *(const float2*)(b_sig + d0);
    u64 a2[4];
#pragma unroll
    for (int bb = 0; bb < 4; bb++) a2[bb] = packxy(bias.x, bias.y);
    const int krow0 = wh * 128;
    for (int k4 = 0; k4 < 128; k4 += 4) {
        float hv[4][4];
#pragma unroll
        for (int bb = 0; bb < 4; bb++)
            *(float4*)hv[bb] = *(const float4*)(embs + (bl[bb] * 11 + 1) * 128 + k4);
#pragma unroll
        for (int q = 0; q < 4; q++) {
            u64 w2 = *(const u64*)(Wt + (krow0 + k4 + q) * WT_LD + d0);
#pragma unroll
            for (int bb = 0; bb < 4; bb++)
                fma2(a2[bb], pack2(hv[bb][q]), w2);
        }
    }

    if (wh == 1) {
#pragma unroll
        for (int bb = 0; bb < 4; bb++) {
            float lo, hi; unpack2(lo, hi, a2[bb]);
            *(float2*)(embs + (bl[bb] * 11 + 2) * 128 + d0) = make_float2(lo, hi);
        }
    }
    __syncthreads();

    if (wh == 0) {
#pragma unroll
        for (int bb = 0; bb < 4; bb++) {
            int bg = b0 + bl[bb];
            int xb = x_batch[bg];
            float2 sg = *(const float2*)(embs + (bl[bb] * 11 + 2) * 128 + d0);
            float2 ep = *(const float2*)(eps + (size_t)bg * DD + d0);
            float2 gs = *(const float2*)(gen_sigma_emb + (size_t)xb * DD + d0);
            float mu0, mu1; unpack2(mu0, mu1, a2[bb]);
            float sgv[2] = {sg.x, sg.y};
            float epv[2] = {ep.x, ep.y};
            float gsv[2] = {gs.x, gs.y};
            float muv[2] = {mu0, mu1};
            float zq[2];
            float klacc = 0.f;
#pragma unroll
            for (int q = 0; q < 2; q++) {
                float isg = softplusf(sgv[q]);
                float zv  = muv[q] + epv[q] * isg;
                zq[q] = zv;
                float sgm = softplusf(gsv[q]);
                float dm  = muv[q] - sgm;
                klacc += logf(sgm / isg)
                       + (isg * isg + dm * dm) / (2.f * sgm * sgm) - 0.5f;
            }
            *(float2*)(embs + (bl[bb] * 11 + 3) * 128 + d0) = make_float2(zq[0], zq[1]);
            __nv_bfloat162 p = __floats2bfloat162_rn(zq[0], zq[1]);
            *((__nv_bfloat162*)(g_zb + (size_t)bg * DD + d0)) = p;
#pragma unroll
            for (int o = 16; o; o >>= 1) klacc += __shfl_xor_sync(0xffffffffu, klacc, o);
            if (lane == 0) atomicAdd(&g_kl[bg], klacc);
        }
    }
    __syncthreads();

    // ---- picked context logits (fp32): 160 (b,c) pairs over 16 warps ----
    const int l4 = lane * 4;
    for (int pp = w; pp < 16 * CC; pp += 16) {
        int b = pp / CC, c = pp - b * CC;
        int bg = b0 + b;
        int n  = ctx[bg * CC + c];
        float4 w4 = ((const float4*)(W_gen + (size_t)n * DD))[lane];
        float4 z4 = *(const float4*)(embs + (b * 11 + 3) * 128 + l4);
        float d = z4.x * w4.x + z4.y * w4.y + z4.z * w4.z + z4.w * w4.w;
#pragma unroll
        for (int o = 16; o; o >>= 1) d += __shfl_xor_sync(0xffffffffu, d, o);
        if (lane == 0) atomicAdd(&g_R[bg], d + b_gen[n]);
    }
}

// ======================== k_logits: two arch paths ========================
#define MT_PER_CTA 8

#if HAS_TCGEN05
__device__ __forceinline__ uint32_t elect_one_pred() {
    uint32_t pred;
    asm volatile(
        "{\n\t.reg .pred p;\n\t"
        "elect.sync _|p, 0xFFFFFFFF;\n\t"
        "selp.b32 %0, 1, 0, p;\n\t}"
        : "=r"(pred));
    return pred;
}
#define MBARRIER_INIT(mbar, cnt) \
    asm volatile("mbarrier.init.shared.b64 [%0], %1;" :: "r"((uint32_t)(mbar)), "r"((uint32_t)(cnt)) : "memory")
#define MBARRIER_WAIT_PARITY(mbar, par) do { \
    uint32_t _m = (uint32_t)(mbar); uint32_t _p = (uint32_t)(par); uint32_t _d; \
    asm volatile("{\n\t.reg .pred p;\n\t" \
        "mbarrier.try_wait.parity.acquire.cta.shared::cta.b64 p, [%1], %2;\n\t" \
        "selp.b32 %0, 1, 0, p;\n\t}" : "=r"(_d) : "r"(_m), "r"(_p) : "memory"); \
    if (!_d) { \
        asm volatile("{\n\t.reg .pred P1;\n\t" \
            "WL_%=:\n\t" \
            "mbarrier.try_wait.parity.acquire.cta.shared::cta.b64 P1, [%0], %1, 0x989680;\n\t" \
            "@P1 bra.uni WD_%=;\n\t" \
            "bra.uni WL_%=;\n\t" \
            "WD_%=:\n\t}" :: "r"(_m), "r"(_p) : "memory"); \
    } } while (0)
#define TCGEN05_ALLOC(smem_addr, nCols) \
    asm volatile("tcgen05.alloc.cta_group::1.sync.aligned.shared::cta.b32 [%0], %1;" \
        :: "r"((uint32_t)(smem_addr)), "r"((uint32_t)(nCols)) : "memory")
#define TCGEN05_DEALLOC(tmem, nCols) \
    asm volatile("tcgen05.dealloc.cta_group::1.sync.aligned.b32 %0, %1;" :: "r"(tmem), "r"((uint32_t)(nCols)))
#define TCGEN05_RELINQUISH() \
    asm volatile("tcgen05.relinquish_alloc_permit.cta_group::1.sync.aligned;")
#define TCGEN05_COMMIT(mbar) \
    asm volatile("tcgen05.commit.cta_group::1.mbarrier::arrive::one.shared::cluster.b64 [%0];" \
        :: "r"((uint32_t)(mbar)) : "memory")
#define TCGEN05_FENCE_BEFORE() asm volatile("tcgen05.fence::before_thread_sync;" ::: "memory")
#define TCGEN05_FENCE_AFTER()  asm volatile("tcgen05.fence::after_thread_sync;" ::: "memory")
#define TCGEN05_WAIT_LD()      asm volatile("tcgen05.wait::ld.sync.aligned;" ::: "memory")
#define FENCE_PROXY_ASYNC()    asm volatile("fence.proxy.async.shared::cta;" ::: "memory")
#define TCGEN05_LD_32X32B_X32(r, tmem_addr) \
    asm volatile( \
        "tcgen05.ld.sync.aligned.32x32b.x32.b32 " \
        "{%0, %1, %2, %3, %4, %5, %6, %7, " \
        " %8, %9, %10, %11, %12, %13, %14, %15, " \
        " %16, %17, %18, %19, %20, %21, %22, %23, " \
        " %24, %25, %26, %27, %28, %29, %30, %31}, [%32];" \
        : "=r"((r)[0]),  "=r"((r)[1]),  "=r"((r)[2]),  "=r"((r)[3]), \
          "=r"((r)[4]),  "=r"((r)[5]),  "=r"((r)[6]),  "=r"((r)[7]), \
          "=r"((r)[8]),  "=r"((r)[9]),  "=r"((r)[10]), "=r"((r)[11]), \
          "=r"((r)[12]), "=r"((r)[13]), "=r"((r)[14]), "=r"((r)[15]), \
          "=r"((r)[16]), "=r"((r)[17]), "=r"((r)[18]), "=r"((r)[19]), \
          "=r"((r)[20]), "=r"((r)[21]), "=r"((r)[22]), "=r"((r)[23]), \
          "=r"((r)[24]), "=r"((r)[25]), "=r"((r)[26]), "=r"((r)[27]), \
          "=r"((r)[28]), "=r"((r)[29]), "=r"((r)[30]), "=r"((r)[31]) \
        : "r"(tmem_addr))
static constexpr uint64_t SMEM_DESC_BASE_SW128 =
    (uint64_t(2) << 61) | (uint64_t(1) << 46) | (uint64_t(64) << 32) | (uint64_t(1) << 16);
#define MAKE_SMEM_DESC(addr) (SMEM_DESC_BASE_SW128 | ((uint64_t)((addr) >> 4) & 0x3FFF))
#define IDESC_LOG 0x08200490u

__device__ __forceinline__ void mma_f16_ss(uint32_t d_tmem, uint64_t a_desc,
                                           uint64_t b_desc, uint32_t idesc, bool accum) {
    uint32_t en = accum ? 1u : 0u;
    asm volatile(
        "{\n\t.reg .pred p;\n\t"
        "setp.ne.u32 p, %4, 0;\n\t"
        "tcgen05.mma.cta_group::1.kind::f16 [%0], %1, %2, %3, {%5,%5,%5,%5}, p;\n\t}"
        :: "r"(d_tmem), "l"(a_desc), "l"(b_desc), "r"(idesc), "r"(en), "r"(0u)
        : "memory");
}

#define SM_TPTR  0
#define SM_MBAR0 8
#define SM_MBAR1 16
#define SM_BG    32
#define SM_W     1024
#define SM_Z0    (1024 + 32768)
#define SM_Z1    (1024 + 65536)

__device__ __forceinline__ void logits_epilogue(int lt, int mt, uint32_t sb, uint32_t tmem,
                                                const float* bg_s, int w, int lane) {
    const int q = lt & 1;
    MBARRIER_WAIT_PARITY(sb + (q ? SM_MBAR1 : SM_MBAR0), (lt >> 1) & 1);
    TCGEN05_FENCE_AFTER();
    const uint32_t woff = ((uint32_t)(w & 3)) << 21;
    const int cb = (w < 4) ? 0 : 64;
    const uint32_t dt = tmem + (uint32_t)(q * 128 + cb) + woff;
    uint32_t r0[32], r1[32];
    TCGEN05_LD_32X32B_X32(r0, dt);
    TCGEN05_LD_32X32B_X32(r1, dt + 32);
    TCGEN05_WAIT_LD();
    TCGEN05_FENCE_BEFORE();
    float acc = 0.f;
#pragma unroll
    for (int c = 0; c < 32; c++) acc += __expf(__uint_as_float(r0[c]) + bg_s[cb + c]);
#pragma unroll
    for (int c = 0; c < 32; c++) acc += __expf(__uint_as_float(r1[c]) + bg_s[cb + 32 + c]);
    atomicAdd(&g_S[mt * 128 + (w & 3) * 32 + lane], acc);
}
#endif  // HAS_TCGEN05

// ---- fallback helpers (baseline sm_103: mma.sync + ldmatrix + cp.async) ----
__device__ __forceinline__ void mma16816(float c[4], const uint32_t a[4],
                                         uint32_t b0, uint32_t b1) {
    asm volatile(
        "mma.sync.aligned.m16n8k16.row.col.f32.bf16.bf16.f32 "
        "{%0,%1,%2,%3},{%4,%5,%6,%7},{%8,%9},{%0,%1,%2,%3};\n"
        : "+f"(c[0]), "+f"(c[1]), "+f"(c[2]), "+f"(c[3])
        : "r"(a[0]), "r"(a[1]), "r"(a[2]), "r"(a[3]), "r"(b0), "r"(b1));
}
__device__ __forceinline__ void ldmatrix_x4(uint32_t r[4], uint32_t addr) {
    asm volatile("ldmatrix.sync.aligned.m8n8.x4.shared.b16 {%0,%1,%2,%3}, [%4];"
        : "=r"(r[0]), "=r"(r[1]), "=r"(r[2]), "=r"(r[3]) : "r"(addr));
}
#define CP_ASYNC16(dst, src) \
    asm volatile("cp.async.cg.shared.global [%0], [%1], 16;" :: "r"(dst), "l"(src))
#define CP_COMMIT()  asm volatile("cp.async.commit_group;" ::: "memory")
#define CP_WAIT(n)   asm volatile("cp.async.wait_group %0;" :: "n"(n) : "memory")

#define TLD    136
#define FB_WS  69632
#define FB_BG  104448
#define SMEM_LOG 104960

__device__ __forceinline__ void fb_prefetch(uint32_t sb, int mt, int p, int tid) {
#pragma unroll
    for (int idx = tid; idx < 2048; idx += 256) {
        int r = idx >> 4, c = idx & 15;
        uint32_t dst = sb + (uint32_t)(p * 34816 + (r * TLD + c * 8) * 2);
        const void* src = (const void*)(g_zb + (size_t)(mt * 128 + r) * DD + c * 8);
        CP_ASYNC16(dst, src);
    }
    CP_COMMIT();
}

__global__ void __launch_bounds__(256, 2) k_logits(const float* __restrict__ W_gen,
                                                   const float* __restrict__ b_gen) {
#if HAS_TCGEN05
    extern __shared__ __align__(16) char smem[];
    const uint32_t sb = smem_to_u32(smem);
    const int tid  = threadIdx.x;
    const int w    = tid >> 5;
    const int lane = tid & 31;
    const int n0   = blockIdx.x * 128;
    const int mt0  = blockIdx.y * MT_PER_CTA;

    if (w == 0) { TCGEN05_ALLOC(sb + SM_TPTR, 256); TCGEN05_RELINQUISH(); }
    if (tid == 0) { MBARRIER_INIT(sb + SM_MBAR0, 1); MBARRIER_INIT(sb + SM_MBAR1, 1); }

    for (int gidx = tid; gidx < 2048; gidx += 256) {
        int r  = gidx >> 4;
        int g8 = gidx & 15;
        int n  = n0 + r;
        uint4 outv = make_uint4(0u, 0u, 0u, 0u);
        if (n < NV) {
            const float4* src = (const float4*)(W_gen + (size_t)n * DD + g8 * 8);
            float4 f0 = src[0], f1 = src[1];
            __nv_bfloat162 h0 = __floats2bfloat162_rn(f0.x, f0.y);
            __nv_bfloat162 h1 = __floats2bfloat162_rn(f0.z, f0.w);
            __nv_bfloat162 h2 = __floats2bfloat162_rn(f1.x, f1.y);
            __nv_bfloat162 h3 = __floats2bfloat162_rn(f1.z, f1.w);
            outv.x = *(uint32_t*)&h0; outv.y = *(uint32_t*)&h1;
            outv.z = *(uint32_t*)&h2; outv.w = *(uint32_t*)&h3;
        }
        int half = g8 >> 3;
        uint32_t boff = (uint32_t)(r * 128 + (g8 & 7) * 16);
        uint32_t sw = boff ^ ((boff >> 3) & 0x70);
        *(uint4*)(smem + SM_W + half * 16384 + sw) = outv;
    }
    if (tid < 128) {
        int n = n0 + tid;
        ((float*)(smem + SM_BG))[tid] = (n < NV) ? b_gen[n] : -88.0f;
    }
    FENCE_PROXY_ASYNC();
    __syncthreads();

    uint32_t tmem;
    asm volatile("ld.shared.b32 %0, [%1];" : "=r"(tmem) : "r"(sb + SM_TPTR));
    const float* bg_s = (const float*)(smem + SM_BG);

    const uint64_t bd0 = MAKE_SMEM_DESC(sb + SM_W);
    const uint64_t bd1 = MAKE_SMEM_DESC(sb + SM_W + 16384);

    for (int lt = 0; lt < MT_PER_CTA; lt++) {
        const int mt = mt0 + lt;
        const int p = lt & 1, k = lt >> 1;
        const uint32_t zoff = p ? SM_Z1 : SM_Z0;
        if (lt >= 2) MBARRIER_WAIT_PARITY(sb + (p ? SM_MBAR1 : SM_MBAR0), (k - 1) & 1);
        for (int gidx = tid; gidx < 2048; gidx += 256) {
            int r = gidx >> 4, g8 = gidx & 15;
            uint4 val = *(const uint4*)(g_zb + ((size_t)(mt * 128 + r)) * DD + g8 * 8);
            int half = g8 >> 3;
            uint32_t boff = (uint32_t)(r * 128 + (g8 & 7) * 16);
            uint32_t sw = boff ^ ((boff >> 3) & 0x70);
            *(uint4*)(smem + zoff + half * 16384 + sw) = val;
        }
        FENCE_PROXY_ASYNC();
        __syncthreads();
        if (w == 0) {
            TCGEN05_FENCE_AFTER();
            if (elect_one_pred()) {
                const uint64_t ad0 = MAKE_SMEM_DESC(sb + zoff);
                const uint64_t ad1 = MAKE_SMEM_DESC(sb + zoff + 16384);
                const uint32_t dt = tmem + (uint32_t)(p * 128);
#pragma unroll
                for (int s = 0; s < 8; s++) {
                    uint64_t ad = ((s >> 2) ? ad1 : ad0) + (uint64_t)((s & 3) * 2);
                    uint64_t bd = ((s >> 2) ? bd1 : bd0) + (uint64_t)((s & 3) * 2);
                    mma_f16_ss(dt, ad, bd, IDESC_LOG, s > 0);
                }
                TCGEN05_COMMIT(sb + (p ? SM_MBAR1 : SM_MBAR0));
            }
        }
        if (lt >= 1) logits_epilogue(lt - 1, mt - 1, sb, tmem, bg_s, w, lane);
    }
    logits_epilogue(MT_PER_CTA - 1, mt0 + MT_PER_CTA - 1, sb, tmem, bg_s, w, lane);
    __syncthreads();
    if (w == 0) TCGEN05_DEALLOC(tmem, 256);
#else
    extern __shared__ __align__(16) char smem[];
    const uint32_t sb = smem_to_u32(smem);
    __nv_bfloat16* Ws = (__nv_bfloat16*)(smem + FB_WS);
    float* bg_s = (float*)(smem + FB_BG);

    const int tid = threadIdx.x;
    const int n0  = blockIdx.x * 128;
    const int mt0 = blockIdx.y * MT_PER_CTA;

    for (int gidx = tid; gidx < 2048; gidx += 256) {
        int r = gidx >> 4, c = gidx & 15;
        int n = n0 + r;
        uint4 outv = make_uint4(0u, 0u, 0u, 0u);
        if (n < NV) {
            const float4* src = (const float4*)(W_gen + (size_t)n * DD + c * 8);
            float4 f0 = src[0], f1 = src[1];
            __nv_bfloat162 h0 = __floats2bfloat162_rn(f0.x, f0.y);
            __nv_bfloat162 h1 = __floats2bfloat162_rn(f0.z, f0.w);
            __nv_bfloat162 h2 = __floats2bfloat162_rn(f1.x, f1.y);
            __nv_bfloat162 h3 = __floats2bfloat162_rn(f1.z, f1.w);
            outv.x = *(uint32_t*)&h0; outv.y = *(uint32_t*)&h1;
            outv.z = *(uint32_t*)&h2; outv.w = *(uint32_t*)&h3;
        }
        *(uint4*)(Ws + r * TLD + c * 8) = outv;
    }
    if (tid < 128) {
        int n = n0 + tid;
        bg_s[tid] = (n < NV) ? b_gen[n] : -88.0f;
    }

    const int w    = tid >> 5;
    const int lane = tid & 31;
    const int g    = lane >> 2;
    const int t    = lane & 3;
    const int wm   = w & 3;
    const int wn   = w >> 2;

    const uint32_t aLane = (uint32_t)(((wm * 32 + (lane & 15)) * TLD + ((lane & 16) >> 1)) * 2);
    uint32_t bAddr[4];
#pragma unroll
    for (int jp = 0; jp < 4; jp++)
        bAddr[jp] = sb + FB_WS +
            (uint32_t)(((wn * 64 + jp * 16 + ((lane & 16) >> 1) + (lane & 7)) * TLD + (lane & 8)) * 2);

    fb_prefetch(sb, mt0, 0, tid);

    for (int lt = 0; lt < MT_PER_CTA; lt++) {
        const int p = lt & 1;
        if (lt + 1 < MT_PER_CTA) { fb_prefetch(sb, mt0 + lt + 1, p ^ 1, tid); CP_WAIT(1); }
        else                     { CP_WAIT(0); }
        __syncthreads();
        const uint32_t aBase0 = sb + (uint32_t)(p * 34816) + aLane;
        const uint32_t aBase1 = aBase0 + (uint32_t)(16 * TLD * 2);

        float acc[2][8][4];
#pragma unroll
        for (int i = 0; i < 2; i++)
#pragma unroll
            for (int j = 0; j < 8; j++)
#pragma unroll
                for (int q = 0; q < 4; q++) acc[i][j][q] = 0.f;

#pragma unroll
        for (int kk = 0; kk < 8; kk++) {
            const uint32_t kb = (uint32_t)(kk * 32);
            uint32_t a0[4], a1[4];
            ldmatrix_x4(a0, aBase0 + kb);
            ldmatrix_x4(a1, aBase1 + kb);
#pragma unroll
            for (int jp = 0; jp < 4; jp++) {
                uint32_t bq[4];
                ldmatrix_x4(bq, bAddr[jp] + kb);
                mma16816(acc[0][2 * jp],     a0, bq[0], bq[1]);
                mma16816(acc[1][2 * jp],     a1, bq[0], bq[1]);
                mma16816(acc[0][2 * jp + 1], a0, bq[2], bq[3]);
                mma16816(acc[1][2 * jp + 1], a1, bq[2], bq[3]);
            }
        }

        const int mt = mt0 + lt;
#pragma unroll
        for (int i = 0; i < 2; i++) {
            float rs0 = 0.f, rs1 = 0.f;
#pragma unroll
            for (int j = 0; j < 8; j++) {
                int nl = wn * 64 + j * 8 + 2 * t;
                float bg0 = bg_s[nl], bg1 = bg_s[nl + 1];
                rs0 += __expf(acc[i][j][0] + bg0) + __expf(acc[i][j][1] + bg1);
                rs1 += __expf(acc[i][j][2] + bg0) + __expf(acc[i][j][3] + bg1);
            }
            rs0 += __shfl_xor_sync(0xffffffffu, rs0, 1);
            rs0 += __shfl_xor_sync(0xffffffffu, rs0, 2);
            rs1 += __shfl_xor_sync(0xffffffffu, rs1, 1);
            rs1 += __shfl_xor_sync(0xffffffffu, rs1, 2);
            if (t == 0) {
                int m = mt * 128 + wm * 32 + i * 16 + g;
                atomicAdd(&g_S[m], rs0);
                atomicAdd(&g_S[m + 8], rs1);
            }
        }
        __syncthreads();
    }
#endif
}

// ---------------- kernel 3: final reduction ----------------
__global__ void __launch_bounds__(1024) k_final(float* __restrict__ out) {
    __shared__ float red[1024];
    const int tid = threadIdx.x;
    float a = 0.f;
    for (int i = tid; i < BB_; i += 1024)
        a += g_kl[i] - g_R[i] + (float)CC * __logf(g_S[i]);
    red[tid] = a;
    __syncthreads();
    for (int s = 512; s; s >>= 1) {
        if (tid < s) red[tid] += red[tid + s];
        __syncthreads();
    }
    if (tid == 0) out[0] = red[0] / (float)BB_;
}

// ---------------- launch ----------------
extern "C" void kernel_launch(void* const* d_in, const int* in_sizes, int n_in,
                              void* d_out, int out_size) {
    const int*   x_batch = (const int*)  d_in[0];
    const int*   ctx     = (const int*)  d_in[1];
    const float* eps     = (const float*)d_in[2];
    const float* inf_emb = (const float*)d_in[3];
    const float* W_aff   = (const float*)d_in[4];
    const float* b_aff   = (const float*)d_in[5];
    const float* W_mu    = (const float*)d_in[6];
    const float* b_mu    = (const float*)d_in[7];
    const float* W_sig   = (const float*)d_in[8];
    const float* b_sig   = (const float*)d_in[9];
    const float* gse     = (const float*)d_in[10];
    const float* W_gen   = (const float*)d_in[11];
    const float* b_gen   = (const float*)d_in[12];

    const int SMEM_A = (256 * WT_LD + 176 * 128) * 4;   // 229376 B
    cudaFuncSetAttribute(k_infnet, cudaFuncAttributeMaxDynamicSharedMemorySize, SMEM_A);
    cudaFuncSetAttribute(k_logits, cudaFuncAttributeMaxDynamicSharedMemorySize, SMEM_LOG);

    k_infnet<<<128, 512, SMEM_A>>>(x_batch, ctx, eps, inf_emb, W_aff, b_aff,
                                   W_mu, b_mu, W_sig, b_sig, gse, W_gen, b_gen);
    k_logits<<<dim3(NPAD / 128, 2), 256, SMEM_LOG>>>(W_gen, b_gen);
    k_final<<<1, 1024>>>((float*)d_out);
}

// round 10
// speedup vs baseline: 1.5164x; 1.2526x over previous
#include <cuda_runtime.h>
#include <cuda_bf16.h>
#include <math.h>
#include <stdint.h>

#define NV   50257
#define NPAD 50304          // 393 * 128
#define DD   128
#define BB_  2048
#define CC   10

#if defined(__CUDA_ARCH__) && (defined(__CUDA_ARCH_FEAT_SM103_ALL) || \
    defined(__CUDA_ARCH_FEAT_SM100_ALL) || defined(__CUDA_ARCH_FAMILY_SPECIFIC__))
#define HAS_TCGEN05 1
#else
#define HAS_TCGEN05 0
#endif

typedef unsigned long long u64;

// ---------------- scratch (static __device__ — allocation-free) ----------------
__device__ __align__(16) __nv_bfloat16 g_zb[BB_ * DD];    // z in bf16
__device__ float g_S[BB_];                                // sum exp(logits) per row
__device__ float g_R[BB_];                                // sum of picked logits per row
__device__ float g_kl[BB_];

// ---------------- common helpers ----------------
__device__ __forceinline__ uint32_t smem_to_u32(const void* p) {
    uint32_t a;
    asm("{ .reg .u64 t; cvta.to.shared.u64 t, %1; cvt.u32.u64 %0, t; }"
        : "=r"(a) : "l"(p));
    return a;
}
__device__ __forceinline__ float softplusf(float x) {
    return fmaxf(x, 0.f) + log1pf(expf(-fabsf(x)));
}
__device__ __forceinline__ void mma16816(float c[4], const uint32_t a[4],
                                         uint32_t b0, uint32_t b1) {
    asm volatile(
        "mma.sync.aligned.m16n8k16.row.col.f32.bf16.bf16.f32 "
        "{%0,%1,%2,%3},{%4,%5,%6,%7},{%8,%9},{%0,%1,%2,%3};\n"
        : "+f"(c[0]), "+f"(c[1]), "+f"(c[2]), "+f"(c[3])
        : "r"(a[0]), "r"(a[1]), "r"(a[2]), "r"(a[3]), "r"(b0), "r"(b1));
}
__device__ __forceinline__ void ldmatrix_x4(uint32_t r[4], uint32_t addr) {
    asm volatile("ldmatrix.sync.aligned.m8n8.x4.shared.b16 {%0,%1,%2,%3}, [%4];"
        : "=r"(r[0]), "=r"(r[1]), "=r"(r[2]), "=r"(r[3]) : "r"(addr));
}
__device__ __forceinline__ uint4 f8_to_bf16x8(float4 f0, float4 f1) {
    __nv_bfloat162 h0 = __floats2bfloat162_rn(f0.x, f0.y);
    __nv_bfloat162 h1 = __floats2bfloat162_rn(f0.z, f0.w);
    __nv_bfloat162 h2 = __floats2bfloat162_rn(f1.x, f1.y);
    __nv_bfloat162 h3 = __floats2bfloat162_rn(f1.z, f1.w);
    return make_uint4(*(uint32_t*)&h0, *(uint32_t*)&h1,
                      *(uint32_t*)&h2, *(uint32_t*)&h3);
}

// ---------------- kernel 1: inference net (tensor-core affine) ----------------
// 128 CTAs x 512 threads. Affine = GEMM: A[192,256]bf16 (rows = b*10+c cat
// rows, padded) x W_aff[128,256]bf16 -> h[160,128] (+b_aff, ReLU) in bf16 smem.
// Then SIMT: hsum (c-sum), mu/sig GEMV fp32 (weights staged over dead A/B),
// KL + z epilogue, ctx-logit tail.
#define ALD   264        // A row stride (bf16): 256 + 8 pad
#define BLD   264        // B (W_aff) row stride
#define HLD   136        // h row stride
#define W2LD  132        // fp32 Wmu/Wsig row stride
#define OFF_A 0
#define OFF_B 101376     // 192*264*2
#define OFF_H 168960     // OFF_B + 128*264*2
#define SMEM_INF 221184  // OFF_H + 192*136*2
#define OFF_HS 135168    // 256*132*4 (after Wt2, inside dead A/B)
#define OFF_SG 143360
#define OFF_Z  151552

__global__ void __launch_bounds__(512) k_infnet(
    const int* __restrict__ x_batch, const int* __restrict__ ctx,
    const float* __restrict__ eps, const float* __restrict__ inf_emb,
    const float* __restrict__ W_aff, const float* __restrict__ b_aff,
    const float* __restrict__ W_mu,  const float* __restrict__ b_mu,
    const float* __restrict__ W_sig, const float* __restrict__ b_sig,
    const float* __restrict__ gen_sigma_emb,
    const float* __restrict__ W_gen, const float* __restrict__ b_gen)
{
    extern __shared__ __align__(16) char smx[];
    __nv_bfloat16* A  = (__nv_bfloat16*)(smx + OFF_A);
    __nv_bfloat16* Bm = (__nv_bfloat16*)(smx + OFF_B);
    __nv_bfloat16* H  = (__nv_bfloat16*)(smx + OFF_H);
    const uint32_t sb = smem_to_u32(smx);

    const int tid  = threadIdx.x;
    const int w    = tid >> 5;
    const int lane = tid & 31;
    const int b0   = blockIdx.x * 16;

    if (tid < 16) { g_S[b0 + tid] = 0.f; g_R[b0 + tid] = 0.f; }

    const uint4 z4 = make_uint4(0u, 0u, 0u, 0u);

    // stage B = W_aff [128 d][256 e] fp32 -> bf16 (rows d = mma "n")
    for (int idx = tid; idx < 128 * 32; idx += 512) {
        int d = idx >> 5, g8 = idx & 31;
        const float4* src = (const float4*)(W_aff + (size_t)d * 256 + g8 * 8);
        *(uint4*)(Bm + d * BLD + g8 * 8) = f8_to_bf16x8(src[0], src[1]);
    }
    if (tid < 128) *(uint4*)(Bm + tid * BLD + 256) = z4;

    // stage A rows: r = b*10+c ; cols 0..127 = center_b, 128..255 = ctx_{b,c}
    for (int idx = tid; idx < 5120; idx += 512) {
        int r = idx >> 5, g8 = idx & 31;
        int b = r / 10, c = r - b * 10;
        int bg = b0 + b;
        int word = (g8 < 16) ? x_batch[bg] : ctx[bg * CC + c];
        const float4* src = (const float4*)(inf_emb + (size_t)word * DD + (g8 & 15) * 8);
        *(uint4*)(A + r * ALD + g8 * 8) = f8_to_bf16x8(src[0], src[1]);
    }
    if (tid < 160) *(uint4*)(A + tid * ALD + 256) = z4;
    for (int idx = tid; idx < 32 * 33; idx += 512) {          // zero rows 160..191
        int r = 160 + idx / 33, gc = idx % 33;
        *(uint4*)(A + r * ALD + gc * 8) = z4;
    }
    __syncthreads();

    // ---- GEMM: 16 warps, warp tile M=48 x N=32, K=256 ----
    const int wm = w & 3, wn = w >> 2;
    const uint32_t aBase = sb + OFF_A +
        (uint32_t)(((wm * 48 + (lane & 15)) * ALD + ((lane & 16) >> 1)) * 2);
    uint32_t bB[2];
#pragma unroll
    for (int np = 0; np < 2; np++)
        bB[np] = sb + OFF_B +
            (uint32_t)(((wn * 32 + np * 16 + ((lane & 16) >> 1) + (lane & 7)) * BLD
                        + (lane & 8)) * 2);

    float acc[3][4][4];
#pragma unroll
    for (int mi = 0; mi < 3; mi++)
#pragma unroll
        for (int nj = 0; nj < 4; nj++)
#pragma unroll
            for (int q = 0; q < 4; q++) acc[mi][nj][q] = 0.f;

#pragma unroll 4
    for (int kk = 0; kk < 16; kk++) {
        const uint32_t kb = (uint32_t)(kk * 32);
        uint32_t am[3][4];
#pragma unroll
        for (int mi = 0; mi < 3; mi++)
            ldmatrix_x4(am[mi], aBase + (uint32_t)(mi * 16 * ALD * 2) + kb);
#pragma unroll
        for (int np = 0; np < 2; np++) {
            uint32_t bq[4];
            ldmatrix_x4(bq, bB[np] + kb);
#pragma unroll
            for (int mi = 0; mi < 3; mi++) {
                mma16816(acc[mi][2 * np],     am[mi], bq[0], bq[1]);
                mma16816(acc[mi][2 * np + 1], am[mi], bq[2], bq[3]);
            }
        }
    }

    // epilogue: + b_aff, ReLU, store h (bf16)
    {
        const int g = lane >> 2, t = lane & 3;
        float2 bav[4];
#pragma unroll
        for (int nj = 0; nj < 4; nj++)
            bav[nj] = *(const float2*)(b_aff + wn * 32 + nj * 8 + 2 * t);
#pragma unroll
        for (int mi = 0; mi < 3; mi++) {
            int row = wm * 48 + mi * 16 + g;
#pragma unroll
            for (int nj = 0; nj < 4; nj++) {
                int col = wn * 32 + nj * 8 + 2 * t;
                float v0 = fmaxf(acc[mi][nj][0] + bav[nj].x, 0.f);
                float v1 = fmaxf(acc[mi][nj][1] + bav[nj].y, 0.f);
                float v2 = fmaxf(acc[mi][nj][2] + bav[nj].x, 0.f);
                float v3 = fmaxf(acc[mi][nj][3] + bav[nj].y, 0.f);
                *(__nv_bfloat162*)(H + row * HLD + col) = __floats2bfloat162_rn(v0, v1);
                *(__nv_bfloat162*)(H + (row + 8) * HLD + col) = __floats2bfloat162_rn(v2, v3);
            }
        }
    }
    __syncthreads();   // A/B dead; H ready

    float* Wt2 = (float*)smx;                 // [256][132] fp32 (mu rows 0..127)
    float* hsm = (float*)(smx + OFF_HS);      // [16][128]
    float* sgb = (float*)(smx + OFF_SG);      // [16][128]
    float* zsm = (float*)(smx + OFF_Z);       // [16][128]
    const int d0 = lane * 4;

    // hsum: warp w owns batch w
    {
        int b = w;
        float s0 = 0.f, s1 = 0.f, s2 = 0.f, s3 = 0.f;
#pragma unroll
        for (int c = 0; c < CC; c++) {
            const __nv_bfloat162* hp = (const __nv_bfloat162*)(H + (b * 10 + c) * HLD + d0);
            float2 p0 = __bfloat1622float2(hp[0]);
            float2 p1 = __bfloat1622float2(hp[1]);
            s0 += p0.x; s1 += p0.y; s2 += p1.x; s3 += p1.y;
        }
        *(float4*)(hsm + b * 128 + d0) = make_float4(s0, s1, s2, s3);
    }
    // stage W_mu^T / W_sig^T fp32
    for (int idx = tid; idx < 128 * 128; idx += 512) {
        int d = idx >> 7, k = idx & 127;
        Wt2[k * W2LD + d]         = W_mu[idx];
        Wt2[(128 + k) * W2LD + d] = W_sig[idx];
    }
    __syncthreads();

    // GEMV: warps wh==0 -> mu, wh==1 -> sig; warp handles batches {wq, wq+8}
    const int wh = w >> 3, wq = w & 7;
    int bL[2] = {wq, wq + 8};
    float4 bias4 = wh ? *(const float4*)(b_sig + d0) : *(const float4*)(b_mu + d0);
    float a4[2][4];
#pragma unroll
    for (int bb = 0; bb < 2; bb++) {
        a4[bb][0] = bias4.x; a4[bb][1] = bias4.y;
        a4[bb][2] = bias4.z; a4[bb][3] = bias4.w;
    }
    const int kr0 = wh * 128;
    for (int k4 = 0; k4 < 128; k4 += 4) {
        float hv[2][4];
#pragma unroll
        for (int bb = 0; bb < 2; bb++)
            *(float4*)hv[bb] = *(const float4*)(hsm + bL[bb] * 128 + k4);
#pragma unroll
        for (int q = 0; q < 4; q++) {
            float4 w4 = *(const float4*)(Wt2 + (kr0 + k4 + q) * W2LD + d0);
#pragma unroll
            for (int bb = 0; bb < 2; bb++) {
                a4[bb][0] += hv[bb][q] * w4.x; a4[bb][1] += hv[bb][q] * w4.y;
                a4[bb][2] += hv[bb][q] * w4.z; a4[bb][3] += hv[bb][q] * w4.w;
            }
        }
    }

    if (wh == 1) {
#pragma unroll
        for (int bb = 0; bb < 2; bb++)
            *(float4*)(sgb + bL[bb] * 128 + d0) =
                make_float4(a4[bb][0], a4[bb][1], a4[bb][2], a4[bb][3]);
    }
    __syncthreads();

    if (wh == 0) {
#pragma unroll
        for (int bb = 0; bb < 2; bb++) {
            int bg = b0 + bL[bb];
            int xb = x_batch[bg];
            float4 sg4 = *(const float4*)(sgb + bL[bb] * 128 + d0);
            float4 ep4 = *(const float4*)(eps + (size_t)bg * DD + d0);
            float4 gs4 = *(const float4*)(gen_sigma_emb + (size_t)xb * DD + d0);
            float sgv[4] = {sg4.x, sg4.y, sg4.z, sg4.w};
            float epv[4] = {ep4.x, ep4.y, ep4.z, ep4.w};
            float gsv[4] = {gs4.x, gs4.y, gs4.z, gs4.w};
            float zq[4];
            float klacc = 0.f;
#pragma unroll
            for (int q = 0; q < 4; q++) {
                float m   = a4[bb][q];
                float isg = softplusf(sgv[q]);
                float zv  = m + epv[q] * isg;
                zq[q] = zv;
                float sgm = softplusf(gsv[q]);
                float dm  = m - sgm;
                klacc += logf(sgm / isg)
                       + (isg * isg + dm * dm) / (2.f * sgm * sgm) - 0.5f;
            }
            *(float4*)(zsm + bL[bb] * 128 + d0) = make_float4(zq[0], zq[1], zq[2], zq[3]);
            __nv_bfloat162 p0 = __floats2bfloat162_rn(zq[0], zq[1]);
            __nv_bfloat162 p1 = __floats2bfloat162_rn(zq[2], zq[3]);
            ((__nv_bfloat162*)(g_zb + (size_t)bg * DD + d0))[0] = p0;
            ((__nv_bfloat162*)(g_zb + (size_t)bg * DD + d0))[1] = p1;
#pragma unroll
            for (int o = 16; o; o >>= 1) klacc += __shfl_xor_sync(0xffffffffu, klacc, o);
            if (lane == 0) g_kl[bg] = klacc;
        }
    }
    __syncthreads();

    // ---- picked context logits (fp32): 160 (b,c) pairs over 16 warps ----
    for (int pp = w; pp < 16 * CC; pp += 16) {
        int b = pp / CC, c = pp - b * CC;
        int bg = b0 + b;
        int n  = ctx[bg * CC + c];
        float4 w4 = ((const float4*)(W_gen + (size_t)n * DD))[lane];
        float4 zz = *(const float4*)(zsm + b * 128 + d0);
        float d = zz.x * w4.x + zz.y * w4.y + zz.z * w4.z + zz.w * w4.w;
#pragma unroll
        for (int o = 16; o; o >>= 1) d += __shfl_xor_sync(0xffffffffu, d, o);
        if (lane == 0) atomicAdd(&g_R[bg], d + b_gen[n]);
    }
}

// ======================== k_logits: two arch paths ========================
#define MT_PER_CTA 8

#if HAS_TCGEN05
__device__ __forceinline__ uint32_t elect_one_pred() {
    uint32_t pred;
    asm volatile(
        "{\n\t.reg .pred p;\n\t"
        "elect.sync _|p, 0xFFFFFFFF;\n\t"
        "selp.b32 %0, 1, 0, p;\n\t}"
        : "=r"(pred));
    return pred;
}
#define MBARRIER_INIT(mbar, cnt) \
    asm volatile("mbarrier.init.shared.b64 [%0], %1;" :: "r"((uint32_t)(mbar)), "r"((uint32_t)(cnt)) : "memory")
#define MBARRIER_WAIT_PARITY(mbar, par) do { \
    uint32_t _m = (uint32_t)(mbar); uint32_t _p = (uint32_t)(par); uint32_t _d; \
    asm volatile("{\n\t.reg .pred p;\n\t" \
        "mbarrier.try_wait.parity.acquire.cta.shared::cta.b64 p, [%1], %2;\n\t" \
        "selp.b32 %0, 1, 0, p;\n\t}" : "=r"(_d) : "r"(_m), "r"(_p) : "memory"); \
    if (!_d) { \
        asm volatile("{\n\t.reg .pred P1;\n\t" \
            "WL_%=:\n\t" \
            "mbarrier.try_wait.parity.acquire.cta.shared::cta.b64 P1, [%0], %1, 0x989680;\n\t" \
            "@P1 bra.uni WD_%=;\n\t" \
            "bra.uni WL_%=;\n\t" \
            "WD_%=:\n\t}" :: "r"(_m), "r"(_p) : "memory"); \
    } } while (0)
#define TCGEN05_ALLOC(smem_addr, nCols) \
    asm volatile("tcgen05.alloc.cta_group::1.sync.aligned.shared::cta.b32 [%0], %1;" \
        :: "r"((uint32_t)(smem_addr)), "r"((uint32_t)(nCols)) : "memory")
#define TCGEN05_DEALLOC(tmem, nCols) \
    asm volatile("tcgen05.dealloc.cta_group::1.sync.aligned.b32 %0, %1;" :: "r"(tmem), "r"((uint32_t)(nCols)))
#define TCGEN05_RELINQUISH() \
    asm volatile("tcgen05.relinquish_alloc_permit.cta_group::1.sync.aligned;")
#define TCGEN05_COMMIT(mbar) \
    asm volatile("tcgen05.commit.cta_group::1.mbarrier::arrive::one.shared::cluster.b64 [%0];" \
        :: "r"((uint32_t)(mbar)) : "memory")
#define TCGEN05_FENCE_BEFORE() asm volatile("tcgen05.fence::before_thread_sync;" ::: "memory")
#define TCGEN05_FENCE_AFTER()  asm volatile("tcgen05.fence::after_thread_sync;" ::: "memory")
#define TCGEN05_WAIT_LD()      asm volatile("tcgen05.wait::ld.sync.aligned;" ::: "memory")
#define FENCE_PROXY_ASYNC()    asm volatile("fence.proxy.async.shared::cta;" ::: "memory")
#define TCGEN05_LD_32X32B_X32(r, tmem_addr) \
    asm volatile( \
        "tcgen05.ld.sync.aligned.32x32b.x32.b32 " \
        "{%0, %1, %2, %3, %4, %5, %6, %7, " \
        " %8, %9, %10, %11, %12, %13, %14, %15, " \
        " %16, %17, %18, %19, %20, %21, %22, %23, " \
        " %24, %25, %26, %27, %28, %29, %30, %31}, [%32];" \
        : "=r"((r)[0]),  "=r"((r)[1]),  "=r"((r)[2]),  "=r"((r)[3]), \
          "=r"((r)[4]),  "=r"((r)[5]),  "=r"((r)[6]),  "=r"((r)[7]), \
          "=r"((r)[8]),  "=r"((r)[9]),  "=r"((r)[10]), "=r"((r)[11]), \
          "=r"((r)[12]), "=r"((r)[13]), "=r"((r)[14]), "=r"((r)[15]), \
          "=r"((r)[16]), "=r"((r)[17]), "=r"((r)[18]), "=r"((r)[19]), \
          "=r"((r)[20]), "=r"((r)[21]), "=r"((r)[22]), "=r"((r)[23]), \
          "=r"((r)[24]), "=r"((r)[25]), "=r"((r)[26]), "=r"((r)[27]), \
          "=r"((r)[28]), "=r"((r)[29]), "=r"((r)[30]), "=r"((r)[31]) \
        : "r"(tmem_addr))
static constexpr uint64_t SMEM_DESC_BASE_SW128 =
    (uint64_t(2) << 61) | (uint64_t(1) << 46) | (uint64_t(64) << 32) | (uint64_t(1) << 16);
#define MAKE_SMEM_DESC(addr) (SMEM_DESC_BASE_SW128 | ((uint64_t)((addr) >> 4) & 0x3FFF))
#define IDESC_LOG 0x08200490u

__device__ __forceinline__ void mma_f16_ss(uint32_t d_tmem, uint64_t a_desc,
                                           uint64_t b_desc, uint32_t idesc, bool accum) {
    uint32_t en = accum ? 1u : 0u;
    asm volatile(
        "{\n\t.reg .pred p;\n\t"
        "setp.ne.u32 p, %4, 0;\n\t"
        "tcgen05.mma.cta_group::1.kind::f16 [%0], %1, %2, %3, {%5,%5,%5,%5}, p;\n\t}"
        :: "r"(d_tmem), "l"(a_desc), "l"(b_desc), "r"(idesc), "r"(en), "r"(0u)
        : "memory");
}

#define SM_TPTR  0
#define SM_MBAR0 8
#define SM_MBAR1 16
#define SM_BG    32
#define SM_W     1024
#define SM_Z0    (1024 + 32768)
#define SM_Z1    (1024 + 65536)

__device__ __forceinline__ void logits_epilogue(int lt, int mt, uint32_t sb, uint32_t tmem,
                                                const float* bg_s, int w, int lane) {
    const int q = lt & 1;
    MBARRIER_WAIT_PARITY(sb + (q ? SM_MBAR1 : SM_MBAR0), (lt >> 1) & 1);
    TCGEN05_FENCE_AFTER();
    const uint32_t woff = ((uint32_t)(w & 3)) << 21;
    const int cb = (w < 4) ? 0 : 64;
    const uint32_t dt = tmem + (uint32_t)(q * 128 + cb) + woff;
    uint32_t r0[32], r1[32];
    TCGEN05_LD_32X32B_X32(r0, dt);
    TCGEN05_LD_32X32B_X32(r1, dt + 32);
    TCGEN05_WAIT_LD();
    TCGEN05_FENCE_BEFORE();
    float acc = 0.f;
#pragma unroll
    for (int c = 0; c < 32; c++) acc += __expf(__uint_as_float(r0[c]) + bg_s[cb + c]);
#pragma unroll
    for (int c = 0; c < 32; c++) acc += __expf(__uint_as_float(r1[c]) + bg_s[cb + 32 + c]);
    atomicAdd(&g_S[mt * 128 + (w & 3) * 32 + lane], acc);
}
#endif  // HAS_TCGEN05

#define CP_ASYNC16(dst, src) \
    asm volatile("cp.async.cg.shared.global [%0], [%1], 16;" :: "r"(dst), "l"(src))
#define CP_COMMIT()  asm volatile("cp.async.commit_group;" ::: "memory")
#define CP_WAIT(n)   asm volatile("cp.async.wait_group %0;" :: "n"(n) : "memory")

#define TLD    136
#define FB_WS  69632
#define FB_BG  104448
#define SMEM_LOG 104960

__device__ __forceinline__ void fb_prefetch(uint32_t sb, int mt, int p, int tid) {
#pragma unroll
    for (int idx = tid; idx < 2048; idx += 256) {
        int r = idx >> 4, c = idx & 15;
        uint32_t dst = sb + (uint32_t)(p * 34816 + (r * TLD + c * 8) * 2);
        const void* src = (const void*)(g_zb + (size_t)(mt * 128 + r) * DD + c * 8);
        CP_ASYNC16(dst, src);
    }
    CP_COMMIT();
}

__global__ void __launch_bounds__(256, 2) k_logits(const float* __restrict__ W_gen,
                                                   const float* __restrict__ b_gen) {
#if HAS_TCGEN05
    extern __shared__ __align__(16) char smem[];
    const uint32_t sb = smem_to_u32(smem);
    const int tid  = threadIdx.x;
    const int w    = tid >> 5;
    const int lane = tid & 31;
    const int n0   = blockIdx.x * 128;
    const int mt0  = blockIdx.y * MT_PER_CTA;

    if (w == 0) { TCGEN05_ALLOC(sb + SM_TPTR, 256); TCGEN05_RELINQUISH(); }
    if (tid == 0) { MBARRIER_INIT(sb + SM_MBAR0, 1); MBARRIER_INIT(sb + SM_MBAR1, 1); }

    for (int gidx = tid; gidx < 2048; gidx += 256) {
        int r  = gidx >> 4;
        int g8 = gidx & 15;
        int n  = n0 + r;
        uint4 outv = make_uint4(0u, 0u, 0u, 0u);
        if (n < NV) {
            const float4* src = (const float4*)(W_gen + (size_t)n * DD + g8 * 8);
            outv = f8_to_bf16x8(src[0], src[1]);
        }
        int half = g8 >> 3;
        uint32_t boff = (uint32_t)(r * 128 + (g8 & 7) * 16);
        uint32_t sw = boff ^ ((boff >> 3) & 0x70);
        *(uint4*)(smem + SM_W + half * 16384 + sw) = outv;
    }
    if (tid < 128) {
        int n = n0 + tid;
        ((float*)(smem + SM_BG))[tid] = (n < NV) ? b_gen[n] : -88.0f;
    }
    FENCE_PROXY_ASYNC();
    __syncthreads();

    uint32_t tmem;
    asm volatile("ld.shared.b32 %0, [%1];" : "=r"(tmem) : "r"(sb + SM_TPTR));
    const float* bg_s = (const float*)(smem + SM_BG);

    const uint64_t bd0 = MAKE_SMEM_DESC(sb + SM_W);
    const uint64_t bd1 = MAKE_SMEM_DESC(sb + SM_W + 16384);

    for (int lt = 0; lt < MT_PER_CTA; lt++) {
        const int mt = mt0 + lt;
        const int p = lt & 1, k = lt >> 1;
        const uint32_t zoff = p ? SM_Z1 : SM_Z0;
        if (lt >= 2) MBARRIER_WAIT_PARITY(sb + (p ? SM_MBAR1 : SM_MBAR0), (k - 1) & 1);
        for (int gidx = tid; gidx < 2048; gidx += 256) {
            int r = gidx >> 4, g8 = gidx & 15;
            uint4 val = *(const uint4*)(g_zb + ((size_t)(mt * 128 + r)) * DD + g8 * 8);
            int half = g8 >> 3;
            uint32_t boff = (uint32_t)(r * 128 + (g8 & 7) * 16);
            uint32_t sw = boff ^ ((boff >> 3) & 0x70);
            *(uint4*)(smem + zoff + half * 16384 + sw) = val;
        }
        FENCE_PROXY_ASYNC();
        __syncthreads();
        if (w == 0) {
            TCGEN05_FENCE_AFTER();
            if (elect_one_pred()) {
                const uint64_t ad0 = MAKE_SMEM_DESC(sb + zoff);
                const uint64_t ad1 = MAKE_SMEM_DESC(sb + zoff + 16384);
                const uint32_t dt = tmem + (uint32_t)(p * 128);
#pragma unroll
                for (int s = 0; s < 8; s++) {
                    uint64_t ad = ((s >> 2) ? ad1 : ad0) + (uint64_t)((s & 3) * 2);
                    uint64_t bd = ((s >> 2) ? bd1 : bd0) + (uint64_t)((s & 3) * 2);
                    mma_f16_ss(dt, ad, bd, IDESC_LOG, s > 0);
                }
                TCGEN05_COMMIT(sb + (p ? SM_MBAR1 : SM_MBAR0));
            }
        }
        if (lt >= 1) logits_epilogue(lt - 1, mt - 1, sb, tmem, bg_s, w, lane);
    }
    logits_epilogue(MT_PER_CTA - 1, mt0 + MT_PER_CTA - 1, sb, tmem, bg_s, w, lane);
    __syncthreads();
    if (w == 0) TCGEN05_DEALLOC(tmem, 256);
#else
    extern __shared__ __align__(16) char smem[];
    const uint32_t sb = smem_to_u32(smem);
    __nv_bfloat16* Ws = (__nv_bfloat16*)(smem + FB_WS);
    float* bg_s = (float*)(smem + FB_BG);

    const int tid = threadIdx.x;
    const int n0  = blockIdx.x * 128;
    const int mt0 = blockIdx.y * MT_PER_CTA;

    for (int gidx = tid; gidx < 2048; gidx += 256) {
        int r = gidx >> 4, c = gidx & 15;
        int n = n0 + r;
        uint4 outv = make_uint4(0u, 0u, 0u, 0u);
        if (n < NV) {
            const float4* src = (const float4*)(W_gen + (size_t)n * DD + c * 8);
            outv = f8_to_bf16x8(src[0], src[1]);
        }
        *(uint4*)(Ws + r * TLD + c * 8) = outv;
    }
    if (tid < 128) {
        int n = n0 + tid;
        bg_s[tid] = (n < NV) ? b_gen[n] : -88.0f;
    }

    const int w    = tid >> 5;
    const int lane = tid & 31;
    const int g    = lane >> 2;
    const int t    = lane & 3;
    const int wm   = w & 3;
    const int wn   = w >> 2;

    const uint32_t aLane = (uint32_t)(((wm * 32 + (lane & 15)) * TLD + ((lane & 16) >> 1)) * 2);
    uint32_t bAddr[4];
#pragma unroll
    for (int jp = 0; jp < 4; jp++)
        bAddr[jp] = sb + FB_WS +
            (uint32_t)(((wn * 64 + jp * 16 + ((lane & 16) >> 1) + (lane & 7)) * TLD + (lane & 8)) * 2);

    fb_prefetch(sb, mt0, 0, tid);

    for (int lt = 0; lt < MT_PER_CTA; lt++) {
        const int p = lt & 1;
        if (lt + 1 < MT_PER_CTA) { fb_prefetch(sb, mt0 + lt + 1, p ^ 1, tid); CP_WAIT(1); }
        else                     { CP_WAIT(0); }
        __syncthreads();
        const uint32_t aBase0 = sb + (uint32_t)(p * 34816) + aLane;
        const uint32_t aBase1 = aBase0 + (uint32_t)(16 * TLD * 2);

        float acc[2][8][4];
#pragma unroll
        for (int i = 0; i < 2; i++)
#pragma unroll
            for (int j = 0; j < 8; j++)
#pragma unroll
                for (int q = 0; q < 4; q++) acc[i][j][q] = 0.f;

#pragma unroll
        for (int kk = 0; kk < 8; kk++) {
            const uint32_t kb = (uint32_t)(kk * 32);
            uint32_t a0[4], a1[4];
            ldmatrix_x4(a0, aBase0 + kb);
            ldmatrix_x4(a1, aBase1 + kb);
#pragma unroll
            for (int jp = 0; jp < 4; jp++) {
                uint32_t bq[4];
                ldmatrix_x4(bq, bAddr[jp] + kb);
                mma16816(acc[0][2 * jp],     a0, bq[0], bq[1]);
                mma16816(acc[1][2 * jp],     a1, bq[0], bq[1]);
                mma16816(acc[0][2 * jp + 1], a0, bq[2], bq[3]);
                mma16816(acc[1][2 * jp + 1], a1, bq[2], bq[3]);
            }
        }

        const int mt = mt0 + lt;
#pragma unroll
        for (int i = 0; i < 2; i++) {
            float rs0 = 0.f, rs1 = 0.f;
#pragma unroll
            for (int j = 0; j < 8; j++) {
                int nl = wn * 64 + j * 8 + 2 * t;
                float bg0 = bg_s[nl], bg1 = bg_s[nl + 1];
                rs0 += __expf(acc[i][j][0] + bg0) + __expf(acc[i][j][1] + bg1);
                rs1 += __expf(acc[i][j][2] + bg0) + __expf(acc[i][j][3] + bg1);
            }
            rs0 += __shfl_xor_sync(0xffffffffu, rs0, 1);
            rs0 += __shfl_xor_sync(0xffffffffu, rs0, 2);
            rs1 += __shfl_xor_sync(0xffffffffu, rs1, 1);
            rs1 += __shfl_xor_sync(0xffffffffu, rs1, 2);
            if (t == 0) {
                int m = mt * 128 + wm * 32 + i * 16 + g;
                atomicAdd(&g_S[m], rs0);
                atomicAdd(&g_S[m + 8], rs1);
            }
        }
        __syncthreads();
    }
#endif
}

// ---------------- kernel 3: final reduction ----------------
__global__ void __launch_bounds__(1024) k_final(float* __restrict__ out) {
    __shared__ float red[1024];
    const int tid = threadIdx.x;
    float a = 0.f;
    for (int i = tid; i < BB_; i += 1024)
        a += g_kl[i] - g_R[i] + (float)CC * __logf(g_S[i]);
    red[tid] = a;
    __syncthreads();
    for (int s = 512; s; s >>= 1) {
        if (tid < s) red[tid] += red[tid + s];
        __syncthreads();
    }
    if (tid == 0) out[0] = red[0] / (float)BB_;
}

// ---------------- launch ----------------
extern "C" void kernel_launch(void* const* d_in, const int* in_sizes, int n_in,
                              void* d_out, int out_size) {
    const int*   x_batch = (const int*)  d_in[0];
    const int*   ctx     = (const int*)  d_in[1];
    const float* eps     = (const float*)d_in[2];
    const float* inf_emb = (const float*)d_in[3];
    const float* W_aff   = (const float*)d_in[4];
    const float* b_aff   = (const float*)d_in[5];
    const float* W_mu    = (const float*)d_in[6];
    const float* b_mu    = (const float*)d_in[7];
    const float* W_sig   = (const float*)d_in[8];
    const float* b_sig   = (const float*)d_in[9];
    const float* gse     = (const float*)d_in[10];
    const float* W_gen   = (const float*)d_in[11];
    const float* b_gen   = (const float*)d_in[12];

    cudaFuncSetAttribute(k_infnet, cudaFuncAttributeMaxDynamicSharedMemorySize, SMEM_INF);
    cudaFuncSetAttribute(k_logits, cudaFuncAttributeMaxDynamicSharedMemorySize, SMEM_LOG);

    k_infnet<<<128, 512, SMEM_INF>>>(x_batch, ctx, eps, inf_emb, W_aff, b_aff,
                                     W_mu, b_mu, W_sig, b_sig, gse, W_gen, b_gen);
    k_logits<<<dim3(NPAD / 128, 2), 256, SMEM_LOG>>>(W_gen, b_gen);
    k_final<<<1, 1024>>>((float*)d_out);
}